// round 1
// baseline (speedup 1.0000x reference)
#include <cuda_runtime.h>

// ============================================================================
// Fused AttentionObstacleEncoder: one CTA per batch element.
//   phase1: t   = relu(obs @ w1 + b1)                      [64,256] -> sh_c
//   phase2: h   = t @ w2 + b2 + pos                        [64,256] -> sh_h
//   per head (4): q,k,v = h @ W[:,h*64:+64] (+bias)        [64,64]
//                 s = softmax(mask(q.k^T/8))               [64,64]
//                 ctx_h = s @ v                            -> sh_c cols h*64..
//   out = ctx @ wo + bo                                    [64,256] -> sh_h
//   pool: mean/max over valid rows -> g[512]
//   g1/g2 MLP + LayerNorm -> out[b,256]
// All GEMM inner loops use fma.rn.f32x2 (packed fp32 pairs = full-rate fp32).
// ============================================================================

typedef unsigned long long ull;

#define DD   256
#define NOB  64
#define NH   4
#define LDA  260   // row stride for 64x256 smem buffers (pad vs bank conflicts)
#define LDH  68    // row stride for 64x64 smem buffers
#define KC   16    // k-chunk for weight staging

// shared memory layout (float offsets)
#define OFF_C    0
#define OFF_H    16640
#define OFF_Q    33280
#define OFF_KT   37632
#define OFF_V    41984
#define OFF_S    46336
#define OFF_W    50688   // 4160 floats: >= 16*260 and >= 3*16*68
#define OFF_G    54848   // 512
#define OFF_OBS  55360   // 256
#define OFF_RED  55616   // 32
#define SMEM_FLOATS 55648
#define SMEM_BYTES  (SMEM_FLOATS * 4)

__device__ __forceinline__ ull f2u(float lo, float hi) {
    ull r; asm("mov.b64 %0, {%1, %2};" : "=l"(r) : "f"(lo), "f"(hi)); return r;
}
__device__ __forceinline__ float2 u2f(ull v) {
    float2 r; asm("mov.b64 {%0, %1}, %2;" : "=f"(r.x), "=f"(r.y) : "l"(v)); return r;
}
__device__ __forceinline__ void fma2(ull& d, ull a, ull b) {
    asm("fma.rn.f32x2 %0, %1, %2, %0;" : "+l"(d) : "l"(a), "l"(b));
}

// ---------------------------------------------------------------------------
// Full GEMM: O[64][256] = A[64][256] @ Wg[256][256] + bias (+ pos)
// Thread (tr=tid>>5, tc=tid&31): rows r0..r0+7, col pairs {2tc,2tc+1}+64p.
// Weight chunks [KC][256] staged in SMEM, register double-buffered.
// ---------------------------------------------------------------------------
__device__ __forceinline__ void gemm_full(
    const float* A, const float* __restrict__ Wg,
    const float* __restrict__ bias, const float* __restrict__ posp,
    float* O, float* ws)
{
    const int tid = threadIdx.x;
    const int tr = tid >> 5, tc = tid & 31;
    const int r0 = tr << 3;

    ull acc[8][4];
#pragma unroll
    for (int j = 0; j < 8; j++)
#pragma unroll
        for (int p = 0; p < 4; p++) acc[j][p] = 0ull;

    // prefetch chunk 0 into registers
    float4 pre[4];
#pragma unroll
    for (int i = 0; i < 4; i++) {
        int t = tid + (i << 8);
        pre[i] = *(const float4*)(Wg + (t >> 6) * DD + ((t & 63) << 2));
    }

#pragma unroll 1
    for (int k0 = 0; k0 < DD; k0 += KC) {
        // store prefetched chunk to smem
#pragma unroll
        for (int i = 0; i < 4; i++) {
            int t = tid + (i << 8);
            *(float4*)(ws + (t >> 6) * LDA + ((t & 63) << 2)) = pre[i];
        }
        __syncthreads();
        // prefetch next chunk (hidden under compute)
        if (k0 + KC < DD) {
#pragma unroll
            for (int i = 0; i < 4; i++) {
                int t = tid + (i << 8);
                pre[i] = *(const float4*)(Wg + (k0 + KC + (t >> 6)) * DD + ((t & 63) << 2));
            }
        }
#pragma unroll
        for (int kk = 0; kk < KC; kk++) {
            ull wv_[4];
#pragma unroll
            for (int p = 0; p < 4; p++)
                wv_[p] = *(const ull*)(ws + kk * LDA + (p << 6) + (tc << 1));
#pragma unroll
            for (int j = 0; j < 8; j++) {
                float a = A[(r0 + j) * LDA + k0 + kk];
                ull a2 = f2u(a, a);
#pragma unroll
                for (int p = 0; p < 4; p++) fma2(acc[j][p], a2, wv_[p]);
            }
        }
        __syncthreads();
    }

    // epilogue
#pragma unroll
    for (int p = 0; p < 4; p++) {
        int c = (p << 6) + (tc << 1);
        float2 bb = *(const float2*)(bias + c);
#pragma unroll
        for (int j = 0; j < 8; j++) {
            float2 v = u2f(acc[j][p]);
            v.x += bb.x; v.y += bb.y;
            if (posp) {
                float2 pv = *(const float2*)(posp + (r0 + j) * DD + c);
                v.x += pv.x; v.y += pv.y;
            }
            *(float2*)(O + (r0 + j) * LDA + c) = v;
        }
    }
}

// ---------------------------------------------------------------------------
// Fused per-head QKV GEMM: [64,256] @ 3x[256,64] (column slice col0).
// q scaled by 1/8 at store; k stored TRANSPOSED (kT[d][j]) for scores GEMM.
// ---------------------------------------------------------------------------
__device__ __forceinline__ void gemm_qkv(
    const float* A,
    const float* __restrict__ Wq, const float* __restrict__ Wk, const float* __restrict__ Wv,
    const float* __restrict__ bq, const float* __restrict__ bk, const float* __restrict__ bv,
    int col0, float* sq, float* skT, float* sv, float* ws)
{
    const int tid = threadIdx.x;
    const int tr = tid >> 5, tc = tid & 31;
    const int r0 = tr << 3;

    ull aq[8], ak[8], av[8];
#pragma unroll
    for (int j = 0; j < 8; j++) { aq[j] = 0ull; ak[j] = 0ull; av[j] = 0ull; }

    float* wsq = ws;
    float* wsk = ws + KC * LDH;
    float* wsv = ws + 2 * KC * LDH;

    const int row = tid >> 4;            // 0..15
    const int c4o = (tid & 15) << 2;     // 0..60

    float4 pq = *(const float4*)(Wq + row * DD + col0 + c4o);
    float4 pk = *(const float4*)(Wk + row * DD + col0 + c4o);
    float4 pv = *(const float4*)(Wv + row * DD + col0 + c4o);

#pragma unroll 1
    for (int k0 = 0; k0 < DD; k0 += KC) {
        *(float4*)(wsq + row * LDH + c4o) = pq;
        *(float4*)(wsk + row * LDH + c4o) = pk;
        *(float4*)(wsv + row * LDH + c4o) = pv;
        __syncthreads();
        if (k0 + KC < DD) {
            pq = *(const float4*)(Wq + (k0 + KC + row) * DD + col0 + c4o);
            pk = *(const float4*)(Wk + (k0 + KC + row) * DD + col0 + c4o);
            pv = *(const float4*)(Wv + (k0 + KC + row) * DD + col0 + c4o);
        }
#pragma unroll
        for (int kk = 0; kk < KC; kk++) {
            ull wq2 = *(const ull*)(wsq + kk * LDH + (tc << 1));
            ull wk2 = *(const ull*)(wsk + kk * LDH + (tc << 1));
            ull wv2 = *(const ull*)(wsv + kk * LDH + (tc << 1));
#pragma unroll
            for (int j = 0; j < 8; j++) {
                float a = A[(r0 + j) * LDA + k0 + kk];
                ull a2 = f2u(a, a);
                fma2(aq[j], a2, wq2);
                fma2(ak[j], a2, wk2);
                fma2(av[j], a2, wv2);
            }
        }
        __syncthreads();
    }

    const int c = tc << 1;
    float2 b_q = *(const float2*)(bq + col0 + c);
    float2 b_k = *(const float2*)(bk + col0 + c);
    float2 b_v = *(const float2*)(bv + col0 + c);
#pragma unroll
    for (int j = 0; j < 8; j++) {
        float2 q = u2f(aq[j]);
        q.x = (q.x + b_q.x) * 0.125f;   // fold 1/sqrt(hd)=1/8 into q
        q.y = (q.y + b_q.y) * 0.125f;
        *(float2*)(sq + (r0 + j) * LDH + c) = q;

        float2 kk_ = u2f(ak[j]);
        kk_.x += b_k.x; kk_.y += b_k.y;
        skT[c * LDH + (r0 + j)] = kk_.x;          // transposed store
        skT[(c + 1) * LDH + (r0 + j)] = kk_.y;

        float2 vv = u2f(av[j]);
        vv.x += b_v.x; vv.y += b_v.y;
        *(float2*)(sv + (r0 + j) * LDH + c) = vv;
    }
}

// ---------------------------------------------------------------------------
__global__ void __launch_bounds__(256, 1)
enc_kernel(const float* __restrict__ obstacles, const int* __restrict__ lengths,
           const float* __restrict__ w1, const float* __restrict__ b1,
           const float* __restrict__ w2, const float* __restrict__ b2,
           const float* __restrict__ pos,
           const float* __restrict__ wq, const float* __restrict__ bq,
           const float* __restrict__ wk, const float* __restrict__ bk,
           const float* __restrict__ wv, const float* __restrict__ bv,
           const float* __restrict__ wo, const float* __restrict__ bo,
           const float* __restrict__ g1w, const float* __restrict__ g1b,
           const float* __restrict__ g2w, const float* __restrict__ g2b,
           const float* __restrict__ ln_g, const float* __restrict__ ln_b,
           float* __restrict__ out)
{
    extern __shared__ float sm[];
    float* sh_c   = sm + OFF_C;
    float* sh_h   = sm + OFF_H;
    float* sh_q   = sm + OFF_Q;
    float* sh_kT  = sm + OFF_KT;
    float* sh_v   = sm + OFF_V;
    float* sh_s   = sm + OFF_S;
    float* sh_w   = sm + OFF_W;
    float* sh_g   = sm + OFF_G;
    float* sh_obs = sm + OFF_OBS;
    float* sh_red = sm + OFF_RED;

    const int b   = blockIdx.x;
    const int tid = threadIdx.x;
    const int len = lengths[b];
    const int tr = tid >> 5, tc = tid & 31;
    const int r0 = tr << 3;
    const int wid = tid >> 5, lane = tid & 31;

    // ---- load obstacles (64x4 = 256 floats) and stage w1 [4][256] ----
    sh_obs[tid] = obstacles[b * (NOB * 4) + tid];
    {
        float4 v = *(const float4*)(w1 + ((tid >> 6) << 8) + ((tid & 63) << 2));
        *(float4*)(sh_w + (tid >> 6) * LDA + ((tid & 63) << 2)) = v;
    }
    __syncthreads();

    // ---- phase 1: t = relu(obs @ w1 + b1) -> sh_c (thread = column) ----
    {
        float wa = sh_w[tid], wb = sh_w[LDA + tid], wc = sh_w[2 * LDA + tid], wd = sh_w[3 * LDA + tid];
        float bb = b1[tid];
#pragma unroll 8
        for (int n = 0; n < NOB; n++) {
            float4 o = *(const float4*)(sh_obs + (n << 2));
            float v = fmaf(o.x, wa, fmaf(o.y, wb, fmaf(o.z, wc, fmaf(o.w, wd, bb))));
            sh_c[n * LDA + tid] = fmaxf(v, 0.0f);
        }
    }
    __syncthreads();

    // ---- phase 2: h = t @ w2 + b2 + pos -> sh_h ----
    gemm_full(sh_c, w2, b2, pos, sh_h, sh_w);
    __syncthreads();

    // ---- attention heads ----
#pragma unroll 1
    for (int hh = 0; hh < NH; hh++) {
        gemm_qkv(sh_h, wq, wk, wv, bq, bk, bv, hh << 6, sh_q, sh_kT, sh_v, sh_w);
        __syncthreads();

        // scores s[i][j] = sum_d q[i][d] * kT[d][j]  (q already pre-scaled)
        {
            ull acc[8];
#pragma unroll
            for (int j = 0; j < 8; j++) acc[j] = 0ull;
#pragma unroll 8
            for (int d = 0; d < 64; d++) {
                ull k2 = *(const ull*)(sh_kT + d * LDH + (tc << 1));
#pragma unroll
                for (int j = 0; j < 8; j++) {
                    float a = sh_q[(r0 + j) * LDH + d];
                    fma2(acc[j], f2u(a, a), k2);
                }
            }
#pragma unroll
            for (int j = 0; j < 8; j++)
                *(float2*)(sh_s + (r0 + j) * LDH + (tc << 1)) = u2f(acc[j]);
        }
        __syncthreads();

        // masked softmax over rows of sh_s (warp w owns rows 8w..8w+7)
        {
            bool v0 = lane < len;
            bool v1 = (lane + 32) < len;
#pragma unroll
            for (int rr = 0; rr < 8; rr++) {
                int r = (wid << 3) + rr;
                float x0 = sh_s[r * LDH + lane];
                float x1 = sh_s[r * LDH + lane + 32];
                float m = fmaxf(v0 ? x0 : -3.4e38f, v1 ? x1 : -3.4e38f);
#pragma unroll
                for (int off = 16; off; off >>= 1)
                    m = fmaxf(m, __shfl_xor_sync(0xffffffffu, m, off));
                float e0 = v0 ? __expf(x0 - m) : 0.0f;
                float e1 = v1 ? __expf(x1 - m) : 0.0f;
                float s = e0 + e1;
#pragma unroll
                for (int off = 16; off; off >>= 1)
                    s += __shfl_xor_sync(0xffffffffu, s, off);
                float inv = __frcp_rn(s);
                sh_s[r * LDH + lane] = e0 * inv;
                sh_s[r * LDH + lane + 32] = e1 * inv;
            }
        }
        __syncthreads();

        // ctx_h = s @ v  -> sh_c columns [hh*64, hh*64+64)
        {
            ull acc[8];
#pragma unroll
            for (int j = 0; j < 8; j++) acc[j] = 0ull;
#pragma unroll 8
            for (int jj = 0; jj < 64; jj++) {
                ull v2 = *(const ull*)(sh_v + jj * LDH + (tc << 1));
#pragma unroll
                for (int j = 0; j < 8; j++) {
                    float a = sh_s[(r0 + j) * LDH + jj];
                    fma2(acc[j], f2u(a, a), v2);
                }
            }
#pragma unroll
            for (int j = 0; j < 8; j++)
                *(float2*)(sh_c + (r0 + j) * LDA + (hh << 6) + (tc << 1)) = u2f(acc[j]);
        }
        __syncthreads();
    }

    // ---- out = ctx @ wo + bo -> sh_h ----
    gemm_full(sh_c, wo, bo, nullptr, sh_h, sh_w);
    __syncthreads();

    // ---- masked mean/max pool (thread = column) ----
    {
        float sum = 0.0f, mx = -3.4e38f;
        for (int n = 0; n < len; n++) {
            float x = sh_h[n * LDA + tid];
            sum += x;
            mx = fmaxf(mx, x);
        }
        sh_g[tid]       = sum / (float)len;
        sh_g[256 + tid] = mx;
    }
    __syncthreads();

    // ---- g1: a1 = relu(g @ g1w + g1b) ----
    float a1;
    {
        float acc = g1b[tid];
#pragma unroll 8
        for (int k = 0; k < 512; k++)
            acc = fmaf(sh_g[k], g1w[k * DD + tid], acc);
        a1 = fmaxf(acc, 0.0f);
    }
    sh_s[tid] = a1;   // reuse scores buffer
    __syncthreads();

    // ---- g2 ----
    float val;
    {
        float acc = g2b[tid];
#pragma unroll 8
        for (int k = 0; k < DD; k++)
            acc = fmaf(sh_s[k], g2w[k * DD + tid], acc);
        val = acc;
    }

    // ---- LayerNorm over 256 (two-pass, matches reference) ----
    float s1 = val;
#pragma unroll
    for (int off = 16; off; off >>= 1) s1 += __shfl_xor_sync(0xffffffffu, s1, off);
    if (lane == 0) sh_red[wid] = s1;
    __syncthreads();
    float mu = 0.0f;
#pragma unroll
    for (int i = 0; i < 8; i++) mu += sh_red[i];
    mu *= (1.0f / 256.0f);
    __syncthreads();

    float d0 = val - mu;
    float s2 = d0 * d0;
#pragma unroll
    for (int off = 16; off; off >>= 1) s2 += __shfl_xor_sync(0xffffffffu, s2, off);
    if (lane == 0) sh_red[wid] = s2;
    __syncthreads();
    float var = 0.0f;
#pragma unroll
    for (int i = 0; i < 8; i++) var += sh_red[i];
    var *= (1.0f / 256.0f);

    float rstd = rsqrtf(var + 1e-5f);
    out[b * DD + tid] = d0 * rstd * ln_g[tid] + ln_b[tid];
}

// ---------------------------------------------------------------------------
extern "C" void kernel_launch(void* const* d_in, const int* in_sizes, int n_in,
                              void* d_out, int out_size)
{
    const float* obstacles = (const float*)d_in[0];
    const int*   lengths   = (const int*)d_in[1];
    const float* w1   = (const float*)d_in[2];
    const float* b1   = (const float*)d_in[3];
    const float* w2   = (const float*)d_in[4];
    const float* b2   = (const float*)d_in[5];
    const float* pos  = (const float*)d_in[6];
    const float* wq   = (const float*)d_in[7];
    const float* bq   = (const float*)d_in[8];
    const float* wk   = (const float*)d_in[9];
    const float* bk   = (const float*)d_in[10];
    const float* wv   = (const float*)d_in[11];
    const float* bv   = (const float*)d_in[12];
    const float* wo   = (const float*)d_in[13];
    const float* bo   = (const float*)d_in[14];
    const float* g1w  = (const float*)d_in[15];
    const float* g1b  = (const float*)d_in[16];
    const float* g2w  = (const float*)d_in[17];
    const float* g2b  = (const float*)d_in[18];
    const float* ln_g = (const float*)d_in[19];
    const float* ln_b = (const float*)d_in[20];
    float* out = (float*)d_out;

    const int B = in_sizes[1];   // lengths element count

    cudaFuncSetAttribute(enc_kernel, cudaFuncAttributeMaxDynamicSharedMemorySize, SMEM_BYTES);
    enc_kernel<<<B, 256, SMEM_BYTES>>>(
        obstacles, lengths, w1, b1, w2, b2, pos,
        wq, bq, wk, bk, wv, bv, wo, bo,
        g1w, g1b, g2w, g2b, ln_g, ln_b, out);
}

// round 2
// speedup vs baseline: 1.0059x; 1.0059x over previous
#include <cuda_runtime.h>

// ============================================================================
// Fused AttentionObstacleEncoder, one CTA (512 threads) per batch element.
// All GEMM inner loops: fma.rn.f32x2, float4 broadcast A-loads, KC=32 weight
// staging through shared memory, 16 warps for latency hiding.
// ============================================================================

typedef unsigned long long ull;

#define DD   256
#define LDH  68      // stride for 64x64 head buffers (16B-aligned rows)
#define KC   32      // k-chunk for weight staging

// shared memory layout (float offsets)
#define OFF_C    0        // 64x256
#define OFF_H    16384    // 64x256
#define OFF_Q    32768    // 64xLDH  (aliased with scores S)
#define OFF_KT   37120    // 64xLDH
#define OFF_V    41472    // 64xLDH
#define OFF_WS   45824    // 8192 floats staging / scratch
#define SMEM_FLOATS 54016
#define SMEM_BYTES  (SMEM_FLOATS * 4)

// scratch sub-offsets inside ws (floats)
#define WS_PS   0      // pool partial sums [512]
#define WS_PM   512    // pool partial max  [512]
#define WS_G    1024   // pooled g [512]
#define WS_T1   1536   // g1 partials [512]
#define WS_A1   2048   // relu(g1) [256]
#define WS_T2   2304   // g2 partials [512]
#define WS_RED  2816   // LN reduction [16]
#define WS_OBS  3072   // obstacles [256]

__device__ __forceinline__ ull f2u(float lo, float hi) {
    ull r; asm("mov.b64 %0, {%1, %2};" : "=l"(r) : "f"(lo), "f"(hi)); return r;
}
__device__ __forceinline__ float2 u2f(ull v) {
    float2 r; asm("mov.b64 {%0, %1}, %2;" : "=f"(r.x), "=f"(r.y) : "l"(v)); return r;
}
__device__ __forceinline__ void fma2(ull& d, ull a, ull b) {
    asm("fma.rn.f32x2 %0, %1, %2, %0;" : "+l"(d) : "l"(a), "l"(b));
}

// ---------------------------------------------------------------------------
// O[64][256] = A[64][256] @ Wg[256][256] + bias (+ pos).
// warp wid owns rows wid*4..+3; lane tc owns col pairs (p*64 + 2*tc), p<4.
// ---------------------------------------------------------------------------
__device__ __forceinline__ void gemm_full(
    const float* A, const float* __restrict__ Wg,
    const float* __restrict__ bias, const float* __restrict__ posp,
    float* O, float* ws)
{
    const int tid = threadIdx.x;
    const int wid = tid >> 5, tc = tid & 31;
    const int r0 = wid << 2;

    ull acc[4][4];
#pragma unroll
    for (int j = 0; j < 4; j++)
#pragma unroll
        for (int p = 0; p < 4; p++) acc[j][p] = 0ull;

    float4 pre[4];
#pragma unroll
    for (int i = 0; i < 4; i++) {
        int t = tid + (i << 9);
        pre[i] = *(const float4*)(Wg + (t >> 6) * DD + ((t & 63) << 2));
    }

#pragma unroll 1
    for (int k0 = 0; k0 < DD; k0 += KC) {
#pragma unroll
        for (int i = 0; i < 4; i++) {
            int t = tid + (i << 9);
            *(float4*)(ws + (t >> 6) * DD + ((t & 63) << 2)) = pre[i];
        }
        __syncthreads();
        if (k0 + KC < DD) {
#pragma unroll
            for (int i = 0; i < 4; i++) {
                int t = tid + (i << 9);
                pre[i] = *(const float4*)(Wg + (k0 + KC + (t >> 6)) * DD + ((t & 63) << 2));
            }
        }
#pragma unroll
        for (int kk4 = 0; kk4 < KC; kk4 += 4) {
            float4 a4[4];
#pragma unroll
            for (int j = 0; j < 4; j++)
                a4[j] = *(const float4*)(A + (r0 + j) * DD + k0 + kk4);
            const float* af = (const float*)a4;
#pragma unroll
            for (int t = 0; t < 4; t++) {
                ull wv2[4];
#pragma unroll
                for (int p = 0; p < 4; p++)
                    wv2[p] = *(const ull*)(ws + (kk4 + t) * DD + (p << 6) + (tc << 1));
#pragma unroll
                for (int j = 0; j < 4; j++) {
                    float a = af[j * 4 + t];
                    ull a2 = f2u(a, a);
#pragma unroll
                    for (int p = 0; p < 4; p++) fma2(acc[j][p], a2, wv2[p]);
                }
            }
        }
        __syncthreads();
    }

#pragma unroll
    for (int p = 0; p < 4; p++) {
        int c = (p << 6) + (tc << 1);
        float2 bb = *(const float2*)(bias + c);
#pragma unroll
        for (int j = 0; j < 4; j++) {
            float2 v = u2f(acc[j][p]);
            v.x += bb.x; v.y += bb.y;
            if (posp) {
                float2 pv = *(const float2*)(posp + (r0 + j) * DD + c);
                v.x += pv.x; v.y += pv.y;
            }
            *(float2*)(O + (r0 + j) * DD + c) = v;
        }
    }
}

// ---------------------------------------------------------------------------
// Fused per-head QKV: [64,256] @ 3x[256,64] column slice col0.
// q scaled by 1/8; k stored transposed kT[d][j]; v row-major.
// ---------------------------------------------------------------------------
__device__ __forceinline__ void gemm_qkv(
    const float* A,
    const float* __restrict__ Wq, const float* __restrict__ Wk, const float* __restrict__ Wv,
    const float* __restrict__ bq, const float* __restrict__ bk, const float* __restrict__ bv,
    int col0, float* sq, float* skT, float* sv, float* ws)
{
    const int tid = threadIdx.x;
    const int wid = tid >> 5, tc = tid & 31;
    const int r0 = wid << 2;

    ull aq[4], ak[4], av[4];
#pragma unroll
    for (int j = 0; j < 4; j++) { aq[j] = 0ull; ak[j] = 0ull; av[j] = 0ull; }

    float* wsq = ws;
    float* wsk = ws + KC * LDH;
    float* wsv = ws + 2 * KC * LDH;

    const int srow = tid >> 4;            // 0..31
    const int sc4  = (tid & 15) << 2;     // 0..60

    float4 pq = *(const float4*)(Wq + srow * DD + col0 + sc4);
    float4 pk = *(const float4*)(Wk + srow * DD + col0 + sc4);
    float4 pv = *(const float4*)(Wv + srow * DD + col0 + sc4);

#pragma unroll 1
    for (int k0 = 0; k0 < DD; k0 += KC) {
        *(float4*)(wsq + srow * LDH + sc4) = pq;
        *(float4*)(wsk + srow * LDH + sc4) = pk;
        *(float4*)(wsv + srow * LDH + sc4) = pv;
        __syncthreads();
        if (k0 + KC < DD) {
            pq = *(const float4*)(Wq + (k0 + KC + srow) * DD + col0 + sc4);
            pk = *(const float4*)(Wk + (k0 + KC + srow) * DD + col0 + sc4);
            pv = *(const float4*)(Wv + (k0 + KC + srow) * DD + col0 + sc4);
        }
#pragma unroll
        for (int kk4 = 0; kk4 < KC; kk4 += 4) {
            float4 a4[4];
#pragma unroll
            for (int j = 0; j < 4; j++)
                a4[j] = *(const float4*)(A + (r0 + j) * DD + k0 + kk4);
            const float* af = (const float*)a4;
#pragma unroll
            for (int t = 0; t < 4; t++) {
                ull wq2 = *(const ull*)(wsq + (kk4 + t) * LDH + (tc << 1));
                ull wk2 = *(const ull*)(wsk + (kk4 + t) * LDH + (tc << 1));
                ull wv2 = *(const ull*)(wsv + (kk4 + t) * LDH + (tc << 1));
#pragma unroll
                for (int j = 0; j < 4; j++) {
                    float a = af[j * 4 + t];
                    ull a2 = f2u(a, a);
                    fma2(aq[j], a2, wq2);
                    fma2(ak[j], a2, wk2);
                    fma2(av[j], a2, wv2);
                }
            }
        }
        __syncthreads();
    }

    const int c = tc << 1;
    float2 b_q = *(const float2*)(bq + col0 + c);
    float2 b_k = *(const float2*)(bk + col0 + c);
    float2 b_v = *(const float2*)(bv + col0 + c);
#pragma unroll
    for (int j = 0; j < 4; j++) {
        float2 q = u2f(aq[j]);
        q.x = (q.x + b_q.x) * 0.125f;
        q.y = (q.y + b_q.y) * 0.125f;
        *(float2*)(sq + (r0 + j) * LDH + c) = q;

        float2 kk_ = u2f(ak[j]);
        kk_.x += b_k.x; kk_.y += b_k.y;
        skT[c * LDH + (r0 + j)] = kk_.x;
        skT[(c + 1) * LDH + (r0 + j)] = kk_.y;

        float2 vv = u2f(av[j]);
        vv.x += b_v.x; vv.y += b_v.y;
        *(float2*)(sv + (r0 + j) * LDH + c) = vv;
    }
}

// ---------------------------------------------------------------------------
__global__ void __launch_bounds__(512, 1)
enc_kernel(const float* __restrict__ obstacles, const int* __restrict__ lengths,
           const float* __restrict__ w1, const float* __restrict__ b1,
           const float* __restrict__ w2, const float* __restrict__ b2,
           const float* __restrict__ pos,
           const float* __restrict__ wq, const float* __restrict__ bq,
           const float* __restrict__ wk, const float* __restrict__ bk,
           const float* __restrict__ wv, const float* __restrict__ bv,
           const float* __restrict__ wo, const float* __restrict__ bo,
           const float* __restrict__ g1w, const float* __restrict__ g1b,
           const float* __restrict__ g2w, const float* __restrict__ g2b,
           const float* __restrict__ ln_g, const float* __restrict__ ln_b,
           float* __restrict__ out)
{
    extern __shared__ float sm[];
    float* sh_c  = sm + OFF_C;
    float* sh_h  = sm + OFF_H;
    float* sh_q  = sm + OFF_Q;
    float* sh_kT = sm + OFF_KT;
    float* sh_v  = sm + OFF_V;
    float* ws    = sm + OFF_WS;
    float* sh_s  = sh_q;    // scores alias Q (row-owner-safe)

    const int b   = blockIdx.x;
    const int tid = threadIdx.x;
    const int len = lengths[b];
    const int wid = tid >> 5, lane = tid & 31;
    const int r0 = wid << 2, tc = lane;

    // ---- stage w1 [4][256] and obstacles [64x4] into ws ----
    if (tid < 256) {
        *(float4*)(ws + (tid << 2)) = *(const float4*)(w1 + (tid << 2));
        ws[WS_OBS + tid] = obstacles[b * 256 + tid];
    }
    __syncthreads();

    // ---- phase 1: t = relu(obs @ w1 + b1) -> sh_c ----
    {
        int col = tid & 255, rh = tid >> 8;
        float wa = ws[col], wb = ws[256 + col], wc_ = ws[512 + col], wd = ws[768 + col];
        float bb = b1[col];
        int n0 = rh << 5;
#pragma unroll 8
        for (int n = n0; n < n0 + 32; n++) {
            float4 o = *(const float4*)(ws + WS_OBS + (n << 2));
            float v = fmaf(o.x, wa, fmaf(o.y, wb, fmaf(o.z, wc_, fmaf(o.w, wd, bb))));
            sh_c[n * DD + col] = fmaxf(v, 0.0f);
        }
    }
    __syncthreads();

    // ---- phase 2: h = t @ w2 + b2 + pos -> sh_h ----
    gemm_full(sh_c, w2, b2, pos, sh_h, ws);

    // ---- attention heads ----
#pragma unroll 1
    for (int hh = 0; hh < 4; hh++) {
        gemm_qkv(sh_h, wq, wk, wv, bq, bk, bv, hh << 6, sh_q, sh_kT, sh_v, ws);
        __syncthreads();

        // scores s[i][j] = sum_d q[i][d]*kT[d][j]  (q pre-scaled by 1/8)
        {
            ull acc[4];
#pragma unroll
            for (int j = 0; j < 4; j++) acc[j] = 0ull;
#pragma unroll 4
            for (int d4 = 0; d4 < 64; d4 += 4) {
                float4 q4[4];
#pragma unroll
                for (int j = 0; j < 4; j++)
                    q4[j] = *(const float4*)(sh_q + (r0 + j) * LDH + d4);
                const float* qf = (const float*)q4;
#pragma unroll
                for (int t = 0; t < 4; t++) {
                    ull k2 = *(const ull*)(sh_kT + (d4 + t) * LDH + (tc << 1));
#pragma unroll
                    for (int j = 0; j < 4; j++) {
                        float a = qf[j * 4 + t];
                        fma2(acc[j], f2u(a, a), k2);
                    }
                }
            }
#pragma unroll
            for (int j = 0; j < 4; j++)
                *(float2*)(sh_s + (r0 + j) * LDH + (tc << 1)) = u2f(acc[j]);
        }
        // no sync: each warp owns its 4 rows of s

        // masked softmax (warp-local rows)
        {
            bool v0 = lane < len;
            bool v1 = (lane + 32) < len;
#pragma unroll
            for (int rr = 0; rr < 4; rr++) {
                int r = r0 + rr;
                float x0 = sh_s[r * LDH + lane];
                float x1 = sh_s[r * LDH + lane + 32];
                float m = fmaxf(v0 ? x0 : -3.4e38f, v1 ? x1 : -3.4e38f);
#pragma unroll
                for (int off = 16; off; off >>= 1)
                    m = fmaxf(m, __shfl_xor_sync(0xffffffffu, m, off));
                float e0 = v0 ? __expf(x0 - m) : 0.0f;
                float e1 = v1 ? __expf(x1 - m) : 0.0f;
                float s = e0 + e1;
#pragma unroll
                for (int off = 16; off; off >>= 1)
                    s += __shfl_xor_sync(0xffffffffu, s, off);
                float inv = __frcp_rn(s);
                sh_s[r * LDH + lane] = e0 * inv;
                sh_s[r * LDH + lane + 32] = e1 * inv;
            }
        }

        // ctx = s @ v -> sh_c cols [hh*64, +64)
        {
            ull acc[4];
#pragma unroll
            for (int j = 0; j < 4; j++) acc[j] = 0ull;
#pragma unroll 4
            for (int jj4 = 0; jj4 < 64; jj4 += 4) {
                float4 s4[4];
#pragma unroll
                for (int j = 0; j < 4; j++)
                    s4[j] = *(const float4*)(sh_s + (r0 + j) * LDH + jj4);
                const float* sf = (const float*)s4;
#pragma unroll
                for (int t = 0; t < 4; t++) {
                    ull v2 = *(const ull*)(sh_v + (jj4 + t) * LDH + (tc << 1));
#pragma unroll
                    for (int j = 0; j < 4; j++) {
                        float a = sf[j * 4 + t];
                        fma2(acc[j], f2u(a, a), v2);
                    }
                }
            }
#pragma unroll
            for (int j = 0; j < 4; j++)
                *(float2*)(sh_c + (r0 + j) * DD + (hh << 6) + (tc << 1)) = u2f(acc[j]);
        }
    }

    // ---- out = ctx @ wo + bo -> sh_h ----
    gemm_full(sh_c, wo, bo, nullptr, sh_h, ws);
    __syncthreads();

    // ---- masked mean/max pool, split across two row-halves ----
    {
        int col = tid & 255, half = tid >> 8;
        int mid = (len + 1) >> 1;
        int nb = half ? mid : 0, ne = half ? len : mid;
        float s = 0.0f, mx = -3.4e38f;
        for (int n = nb; n < ne; n++) {
            float x = sh_h[n * DD + col];
            s += x; mx = fmaxf(mx, x);
        }
        ws[WS_PS + tid] = s;
        ws[WS_PM + tid] = mx;
    }
    __syncthreads();
    if (tid < 256) {
        ws[WS_G + tid]       = (ws[WS_PS + tid] + ws[WS_PS + 256 + tid]) / (float)len;
        ws[WS_G + 256 + tid] = fmaxf(ws[WS_PM + tid], ws[WS_PM + 256 + tid]);
    }
    __syncthreads();

    // ---- g1 (512 k split over two thread-halves) ----
    {
        int col = tid & 255, half = tid >> 8;
        float acc = 0.0f;
        int kb = half << 8;
#pragma unroll 8
        for (int k = kb; k < kb + 256; k++)
            acc = fmaf(ws[WS_G + k], g1w[k * DD + col], acc);
        ws[WS_T1 + tid] = acc;
    }
    __syncthreads();
    if (tid < 256)
        ws[WS_A1 + tid] = fmaxf(ws[WS_T1 + tid] + ws[WS_T1 + 256 + tid] + g1b[tid], 0.0f);
    __syncthreads();

    // ---- g2 (256 k split) ----
    {
        int col = tid & 255, half = tid >> 8;
        float acc = 0.0f;
        int kb = half << 7;
#pragma unroll 8
        for (int k = kb; k < kb + 128; k++)
            acc = fmaf(ws[WS_A1 + k], g2w[k * DD + col], acc);
        ws[WS_T2 + tid] = acc;
    }
    __syncthreads();
    float val = 0.0f;
    if (tid < 256)
        val = ws[WS_T2 + tid] + ws[WS_T2 + 256 + tid] + g2b[tid];

    // ---- LayerNorm over 256 (first 8 warps carry data) ----
    float s1 = val;
#pragma unroll
    for (int off = 16; off; off >>= 1) s1 += __shfl_xor_sync(0xffffffffu, s1, off);
    if (lane == 0) ws[WS_RED + wid] = s1;
    __syncthreads();
    float mu = 0.0f;
#pragma unroll
    for (int i = 0; i < 8; i++) mu += ws[WS_RED + i];
    mu *= (1.0f / 256.0f);
    __syncthreads();

    float d0 = val - mu;
    float s2 = d0 * d0;
#pragma unroll
    for (int off = 16; off; off >>= 1) s2 += __shfl_xor_sync(0xffffffffu, s2, off);
    if (lane == 0) ws[WS_RED + wid] = s2;
    __syncthreads();
    float var = 0.0f;
#pragma unroll
    for (int i = 0; i < 8; i++) var += ws[WS_RED + i];
    var *= (1.0f / 256.0f);

    if (tid < 256)
        out[b * DD + tid] = d0 * rsqrtf(var + 1e-5f) * ln_g[tid] + ln_b[tid];
}

// ---------------------------------------------------------------------------
extern "C" void kernel_launch(void* const* d_in, const int* in_sizes, int n_in,
                              void* d_out, int out_size)
{
    const float* obstacles = (const float*)d_in[0];
    const int*   lengths   = (const int*)d_in[1];
    const float* w1   = (const float*)d_in[2];
    const float* b1   = (const float*)d_in[3];
    const float* w2   = (const float*)d_in[4];
    const float* b2   = (const float*)d_in[5];
    const float* pos  = (const float*)d_in[6];
    const float* wq   = (const float*)d_in[7];
    const float* bq   = (const float*)d_in[8];
    const float* wk   = (const float*)d_in[9];
    const float* bk   = (const float*)d_in[10];
    const float* wv   = (const float*)d_in[11];
    const float* bv   = (const float*)d_in[12];
    const float* wo   = (const float*)d_in[13];
    const float* bo   = (const float*)d_in[14];
    const float* g1w  = (const float*)d_in[15];
    const float* g1b  = (const float*)d_in[16];
    const float* g2w  = (const float*)d_in[17];
    const float* g2b  = (const float*)d_in[18];
    const float* ln_g = (const float*)d_in[19];
    const float* ln_b = (const float*)d_in[20];
    float* out = (float*)d_out;

    const int B = in_sizes[1];

    cudaFuncSetAttribute(enc_kernel, cudaFuncAttributeMaxDynamicSharedMemorySize, SMEM_BYTES);
    enc_kernel<<<B, 512, SMEM_BYTES>>>(
        obstacles, lengths, w1, b1, w2, b2, pos,
        wq, bq, wk, bk, wv, bv, wo, bo,
        g1w, g1b, g2w, g2b, ln_g, ln_b, out);
}

// round 4
// speedup vs baseline: 1.4252x; 1.4168x over previous
#include <cuda_runtime.h>

// ============================================================================
// AttentionObstacleEncoder via tf32 mma.sync.m16n8k8 (3xTF32 precision).
//
// Fold: h = t@w2 + b2 + pos  =>  Q = t@(w2@wq) + [(pos+b2)@wq + bq]  (etc).
// Prep kernels (per launch): fold weights, fold pos/bias into per-row bias
// tables, pack weights as tf32 hi/lo fragment-ordered uint4 arrays.
// Main kernel: one CTA (512 thr) per batch element, all GEMMs on tensor cores.
// ============================================================================

typedef unsigned int u32;

#define LDT 260     // stride for [64][256] fp32 smem (260%32==4 -> no conflicts)
#define LDK 68      // stride for [64][64] head buffers

// smem float offsets
#define OFF_T   0        // t   [64][260] fp32 (later: attention output)
#define OFF_Q   16640    // Q   [64][260] fp32 (later: ctx)
#define OFF_K   33280    // K_h [64][68]
#define OFF_VT  37632    // VT_h[64][68]  (V transposed)
#define OFF_S   41984    // S/P [64][68]  + scratch alias
#define SMEM_FLOATS 46336
#define SMEM_BYTES  (SMEM_FLOATS * 4)

// scratch sub-offsets inside S-buffer region (floats)
#define WS_PS   0
#define WS_PM   512
#define WS_G    1024
#define WS_T1   1536
#define WS_A1   2048
#define WS_T2   2304
#define WS_RED  2816
#define WS_OBS  2848
#define WS_W1   3104

// device scratch: folded weights, bias tables, packed tf32 hi/lo fragments
__device__ float g_wf[3 * 65536];        // w2@{wq,wk,wv} fp32 (q pre-scaled 1/8)
__device__ float g_posb[3 * 16384];      // [(pos+b2)@wx + bx] per-row bias
__device__ uint4 g_wr[4 * 32768];        // packed: {wq',wk',wv',wo} hi/lo

__device__ __forceinline__ u32 cvt_tf32(float f) {
    u32 r; asm("cvt.rna.tf32.f32 %0, %1;" : "=r"(r) : "f"(f)); return r;
}
__device__ __forceinline__ void hilo(float x, u32& h, u32& l) {
    h = cvt_tf32(x);
    l = cvt_tf32(x - __uint_as_float(h));
}
__device__ __forceinline__ void mma8(float* c, u32 a0, u32 a1, u32 a2, u32 a3,
                                     u32 b0, u32 b1) {
    asm("mma.sync.aligned.m16n8k8.row.col.f32.tf32.tf32.f32 "
        "{%0,%1,%2,%3},{%4,%5,%6,%7},{%8,%9},{%0,%1,%2,%3};"
        : "+f"(c[0]), "+f"(c[1]), "+f"(c[2]), "+f"(c[3])
        : "r"(a0), "r"(a1), "r"(a2), "r"(a3), "r"(b0), "r"(b1));
}
// 3xTF32: al*bh + ah*bl + ah*bh
__device__ __forceinline__ void mma3(float* c, const u32* ah, const u32* al,
                                     u32 bh0, u32 bh1, u32 bl0, u32 bl1) {
    mma8(c, al[0], al[1], al[2], al[3], bh0, bh1);
    mma8(c, ah[0], ah[1], ah[2], ah[3], bl0, bl1);
    mma8(c, ah[0], ah[1], ah[2], ah[3], bh0, bh1);
}

// ============================================================================
// Prep kernels (run every launch; deterministic; ~25us total)
// ============================================================================

// g_wf[m][k][c] = sum_d w2[k][d]*wx[d][c]   (m=0 scaled by 1/8). grid 768x256.
__global__ void fold_k(const float* __restrict__ w2, const float* __restrict__ wq,
                       const float* __restrict__ wk, const float* __restrict__ wv)
{
    int m = blockIdx.x >> 8, k = blockIdx.x & 255, c = threadIdx.x;
    const float* wx = (m == 0) ? wq : (m == 1) ? wk : wv;
    float acc = 0.0f;
#pragma unroll 8
    for (int d = 0; d < 256; d++)
        acc = fmaf(__ldg(w2 + k * 256 + d), __ldg(wx + d * 256 + c), acc);
    if (m == 0) acc *= 0.125f;
    g_wf[m * 65536 + k * 256 + c] = acc;
}

// g_posb[m][n][c] = ((pos[n]+b2)@wx + bx)[c]  (m=0 scaled 1/8). grid 192x256.
__global__ void posfold_k(const float* __restrict__ pos, const float* __restrict__ b2,
                          const float* __restrict__ wq, const float* __restrict__ wk,
                          const float* __restrict__ wv, const float* __restrict__ bq,
                          const float* __restrict__ bk, const float* __restrict__ bv)
{
    int m = blockIdx.x >> 6, n = blockIdx.x & 63, c = threadIdx.x;
    const float* wx = (m == 0) ? wq : (m == 1) ? wk : wv;
    const float* bx = (m == 0) ? bq : (m == 1) ? bk : bv;
    float acc = __ldg(bx + c);
#pragma unroll 8
    for (int d = 0; d < 256; d++)
        acc = fmaf(__ldg(pos + n * 256 + d) + __ldg(b2 + d), __ldg(wx + d * 256 + c), acc);
    if (m == 0) acc *= 0.125f;
    g_posb[m * 16384 + n * 256 + c] = acc;
}

// Pack W[256][256] -> [ntile][s][lane] uint4 (b0_hi,b0_lo,b1_hi,b1_lo).
// b0 = W[8s + (lane&3)][8*ntile + (lane>>2)], b1 = W[8s+4+(lane&3)][same n].
// grid 512x256 over 4*32768 uint4.
__global__ void pack_k(const float* __restrict__ wo)
{
    int idx = blockIdx.x * 256 + threadIdx.x;      // 0 .. 131071
    int m = idx >> 15;
    int u = idx & 32767;
    int ntile = u >> 10;
    int s = (u >> 5) & 31;
    int lane = u & 31;
    int n = ntile * 8 + (lane >> 2);
    int k = s * 8 + (lane & 3);
    const float* W = (m < 3) ? (g_wf + m * 65536) : wo;
    float b0 = W[k * 256 + n];
    float b1 = W[(k + 4) * 256 + n];
    uint4 r;
    hilo(b0, r.x, r.y);
    hilo(b1, r.z, r.w);
    g_wr[idx] = r;
}

// ============================================================================
// Main kernel device pieces
// ============================================================================

// A-fragment (m16 rows at m0, k8 at k0) from fp32 smem, stride ld -> hi/lo.
__device__ __forceinline__ void load_a(const float* A, int ld, int m0, int k0,
                                       int g, int t, u32* ah, u32* al)
{
    float a0 = A[(m0 + g) * ld + k0 + t];
    float a1 = A[(m0 + 8 + g) * ld + k0 + t];
    float a2 = A[(m0 + g) * ld + k0 + 4 + t];
    float a3 = A[(m0 + 8 + g) * ld + k0 + 4 + t];
    hilo(a0, ah[0], al[0]);
    hilo(a1, ah[1], al[1]);
    hilo(a2, ah[2], al[2]);
    hilo(a3, ah[3], al[3]);
}

// Big GEMM: Out[64][256] = A[64][256] @ W(packed) + bias.
// 16 warps: mrow=wid&3 (m0=16*mrow), ncol=wid>>2 (64 cols = 8 ntiles).
// biasRows: per-row bias table [64][256] (g_posb) or nullptr -> biasVec[256].
__device__ __forceinline__ void gemm_big(
    const float* A, const uint4* __restrict__ Wp,
    const float* __restrict__ biasRows, const float* __restrict__ biasVec,
    float* Out)
{
    const int wid = threadIdx.x >> 5, lane = threadIdx.x & 31;
    const int g = lane >> 2, t = lane & 3;
    const int m0 = (wid & 3) << 4;
    const int ncol = wid >> 2;
    const int ntbase = ncol << 3;

    float c[8][4];
#pragma unroll
    for (int i = 0; i < 8; i++)
#pragma unroll
        for (int j = 0; j < 4; j++) c[i][j] = 0.0f;

#pragma unroll 1
    for (int s = 0; s < 32; s++) {
        u32 ah[4], al[4];
        load_a(A, LDT, m0, s << 3, g, t, ah, al);
#pragma unroll
        for (int half = 0; half < 2; half++) {
            uint4 w[4];
#pragma unroll
            for (int i = 0; i < 4; i++) {
                int nt = half * 4 + i;
                w[i] = Wp[((ntbase + nt) << 10) + (s << 5) + lane];
            }
#pragma unroll
            for (int i = 0; i < 4; i++)
                mma3(c[half * 4 + i], ah, al, w[i].x, w[i].z, w[i].y, w[i].w);
        }
    }

#pragma unroll
    for (int nt = 0; nt < 8; nt++) {
        int col = (ncol << 6) + (nt << 3) + (t << 1);
        float2 bA, bB;
        if (biasRows) {
            bA = *(const float2*)(biasRows + (m0 + g) * 256 + col);
            bB = *(const float2*)(biasRows + (m0 + 8 + g) * 256 + col);
        } else {
            bA = *(const float2*)(biasVec + col);
            bB = bA;
        }
        Out[(m0 + g) * LDT + col]         = c[nt][0] + bA.x;
        Out[(m0 + g) * LDT + col + 1]     = c[nt][1] + bA.y;
        Out[(m0 + 8 + g) * LDT + col]     = c[nt][2] + bB.x;
        Out[(m0 + 8 + g) * LDT + col + 1] = c[nt][3] + bB.y;
    }
}

// Per-head K/V GEMM: warps 0-7 compute K_h [64][68], warps 8-15 VT_h [64][68].
__device__ __forceinline__ void gemm_kv(
    const float* A, int h, float* Kh, float* VTh)
{
    const int wid = threadIdx.x >> 5, lane = threadIdx.x & 31;
    const int g = lane >> 2, t = lane & 3;
    const int lw = wid & 7, isV = wid >> 3;
    const int m0 = (lw & 3) << 4;
    const int ncol2 = lw >> 2;                 // 0..1 -> 32 cols each
    const uint4* __restrict__ Wp = g_wr + ((1 + isV) << 15);
    const float* __restrict__ biasRows = g_posb + ((1 + isV) << 14);

    float c[4][4];
#pragma unroll
    for (int i = 0; i < 4; i++)
#pragma unroll
        for (int j = 0; j < 4; j++) c[i][j] = 0.0f;

#pragma unroll 1
    for (int s = 0; s < 32; s++) {
        u32 ah[4], al[4];
        load_a(A, LDT, m0, s << 3, g, t, ah, al);
        uint4 w[4];
#pragma unroll
        for (int i = 0; i < 4; i++) {
            int ntg = (h << 3) + (ncol2 << 2) + i;
            w[i] = Wp[(ntg << 10) + (s << 5) + lane];
        }
#pragma unroll
        for (int i = 0; i < 4; i++)
            mma3(c[i], ah, al, w[i].x, w[i].z, w[i].y, w[i].w);
    }

#pragma unroll
    for (int nt = 0; nt < 4; nt++) {
        int nl = (ncol2 << 5) + (nt << 3) + (t << 1);    // local col in head
        int colg = (h << 6) + nl;
        float2 bA = *(const float2*)(biasRows + (m0 + g) * 256 + colg);
        float2 bB = *(const float2*)(biasRows + (m0 + 8 + g) * 256 + colg);
        if (!isV) {
            Kh[(m0 + g) * LDK + nl]         = c[nt][0] + bA.x;
            Kh[(m0 + g) * LDK + nl + 1]     = c[nt][1] + bA.y;
            Kh[(m0 + 8 + g) * LDK + nl]     = c[nt][2] + bB.x;
            Kh[(m0 + 8 + g) * LDK + nl + 1] = c[nt][3] + bB.y;
        } else {
            VTh[nl * LDK + m0 + g]           = c[nt][0] + bA.x;
            VTh[(nl + 1) * LDK + m0 + g]     = c[nt][1] + bA.y;
            VTh[nl * LDK + m0 + 8 + g]       = c[nt][2] + bB.x;
            VTh[(nl + 1) * LDK + m0 + 8 + g] = c[nt][3] + bB.y;
        }
    }
}

// 64x64x64 GEMM with both operands in smem: Out = A(strideA) @ B(k,n)=Bm[n][k].
// colA: column offset into A rows.  Writes Out[m][n] (stride ldo, col off colO).
__device__ __forceinline__ void gemm_small(
    const float* A, int lda, int colA,
    const float* Bm,                 // [64][LDK], element (n,k) at Bm[n*LDK+k]
    float* Out, int ldo, int colO)
{
    const int wid = threadIdx.x >> 5, lane = threadIdx.x & 31;
    const int g = lane >> 2, t = lane & 3;
    const int m0 = (wid & 3) << 4;
    const int ncol = wid >> 2;

    float c[2][4];
#pragma unroll
    for (int i = 0; i < 2; i++)
#pragma unroll
        for (int j = 0; j < 4; j++) c[i][j] = 0.0f;

#pragma unroll 1
    for (int s = 0; s < 8; s++) {
        int k0 = s << 3;
        u32 ah[4], al[4];
        load_a(A + colA, lda, m0, k0, g, t, ah, al);
#pragma unroll
        for (int nt = 0; nt < 2; nt++) {
            int n0 = (ncol << 4) + (nt << 3);
            float b0f = Bm[(n0 + g) * LDK + k0 + t];
            float b1f = Bm[(n0 + g) * LDK + k0 + 4 + t];
            u32 bh0, bl0, bh1, bl1;
            hilo(b0f, bh0, bl0);
            hilo(b1f, bh1, bl1);
            mma3(c[nt], ah, al, bh0, bh1, bl0, bl1);
        }
    }

#pragma unroll
    for (int nt = 0; nt < 2; nt++) {
        int n0 = (ncol << 4) + (nt << 3) + (t << 1);
        Out[(m0 + g) * ldo + colO + n0]         = c[nt][0];
        Out[(m0 + g) * ldo + colO + n0 + 1]     = c[nt][1];
        Out[(m0 + 8 + g) * ldo + colO + n0]     = c[nt][2];
        Out[(m0 + 8 + g) * ldo + colO + n0 + 1] = c[nt][3];
    }
}

// ============================================================================
__global__ void __launch_bounds__(512, 1)
enc_kernel(const float* __restrict__ obstacles, const int* __restrict__ lengths,
           const float* __restrict__ w1, const float* __restrict__ b1,
           const float* __restrict__ bo,
           const float* __restrict__ g1w, const float* __restrict__ g1b,
           const float* __restrict__ g2w, const float* __restrict__ g2b,
           const float* __restrict__ ln_g, const float* __restrict__ ln_b,
           float* __restrict__ out)
{
    extern __shared__ float sm[];
    float* Ts  = sm + OFF_T;
    float* Qs  = sm + OFF_Q;
    float* Kh  = sm + OFF_K;
    float* VTh = sm + OFF_VT;
    float* Ss  = sm + OFF_S;
    float* ws  = sm + OFF_S;     // scratch alias

    const int b   = blockIdx.x;
    const int tid = threadIdx.x;
    const int len = lengths[b];
    const int wid = tid >> 5, lane = tid & 31;

    // ---- stage w1 + obstacles ----
    if (tid < 256) {
        *(float4*)(ws + WS_W1 + (tid << 2)) = *(const float4*)(w1 + (tid << 2));
        ws[WS_OBS + tid] = obstacles[b * 256 + tid];
    }
    __syncthreads();

    // ---- phase 1: t = relu(obs @ w1 + b1) -> Ts fp32 ----
    {
        int col = tid & 255, rh = tid >> 8;
        float wa = ws[WS_W1 + col], wb = ws[WS_W1 + 256 + col];
        float wc_ = ws[WS_W1 + 512 + col], wd = ws[WS_W1 + 768 + col];
        float bb = b1[col];
        int n0 = rh << 5;
#pragma unroll 8
        for (int n = n0; n < n0 + 32; n++) {
            float4 o = *(const float4*)(ws + WS_OBS + (n << 2));
            float v = fmaf(o.x, wa, fmaf(o.y, wb, fmaf(o.z, wc_, fmaf(o.w, wd, bb))));
            Ts[n * LDT + col] = fmaxf(v, 0.0f);
        }
    }
    __syncthreads();

    // ---- Q = t @ wq' + posbq  (scaled 1/8 already) ----
    gemm_big(Ts, g_wr, g_posb, nullptr, Qs);
    __syncthreads();

    // ---- attention heads ----
#pragma unroll 1
    for (int h = 0; h < 4; h++) {
        gemm_kv(Ts, h, Kh, VTh);
        __syncthreads();

        // scores S = Q_h @ K_h^T  -> Ss
        gemm_small(Qs, LDT, h << 6, Kh, Ss, LDK, 0);
        __syncthreads();

        // masked softmax (warp wid owns rows 4*wid..+3)
        {
            bool v0 = lane < len;
            bool v1 = (lane + 32) < len;
#pragma unroll
            for (int rr = 0; rr < 4; rr++) {
                int r = (wid << 2) + rr;
                float x0 = Ss[r * LDK + lane];
                float x1 = Ss[r * LDK + lane + 32];
                float m = fmaxf(v0 ? x0 : -3.4e38f, v1 ? x1 : -3.4e38f);
#pragma unroll
                for (int off = 16; off; off >>= 1)
                    m = fmaxf(m, __shfl_xor_sync(0xffffffffu, m, off));
                float e0 = v0 ? __expf(x0 - m) : 0.0f;
                float e1 = v1 ? __expf(x1 - m) : 0.0f;
                float s = e0 + e1;
#pragma unroll
                for (int off = 16; off; off >>= 1)
                    s += __shfl_xor_sync(0xffffffffu, s, off);
                float inv = __frcp_rn(s);
                Ss[r * LDK + lane] = e0 * inv;
                Ss[r * LDK + lane + 32] = e1 * inv;
            }
        }
        __syncthreads();

        // ctx_h = P @ V_h -> overwrite Q cols [64h, 64h+64)
        gemm_small(Ss, LDK, 0, VTh, Qs, LDT, h << 6);
        __syncthreads();
    }

    // ---- out = ctx @ wo + bo -> Ts ----
    gemm_big(Qs, g_wr + 3 * 32768, nullptr, bo, Ts);
    __syncthreads();

    // ---- masked mean/max pool ----
    {
        int col = tid & 255, half = tid >> 8;
        int mid = (len + 1) >> 1;
        int nb = half ? mid : 0, ne = half ? len : mid;
        float s = 0.0f, mx = -3.4e38f;
        for (int n = nb; n < ne; n++) {
            float x = Ts[n * LDT + col];
            s += x; mx = fmaxf(mx, x);
        }
        ws[WS_PS + tid] = s;
        ws[WS_PM + tid] = mx;
    }
    __syncthreads();
    if (tid < 256) {
        ws[WS_G + tid]       = (ws[WS_PS + tid] + ws[WS_PS + 256 + tid]) / (float)len;
        ws[WS_G + 256 + tid] = fmaxf(ws[WS_PM + tid], ws[WS_PM + 256 + tid]);
    }
    __syncthreads();

    // ---- g1 ----
    {
        int col = tid & 255, half = tid >> 8;
        float acc = 0.0f;
        int kb = half << 8;
#pragma unroll 8
        for (int k = kb; k < kb + 256; k++)
            acc = fmaf(ws[WS_G + k], g1w[k * 256 + col], acc);
        ws[WS_T1 + tid] = acc;
    }
    __syncthreads();
    if (tid < 256)
        ws[WS_A1 + tid] = fmaxf(ws[WS_T1 + tid] + ws[WS_T1 + 256 + tid] + g1b[tid], 0.0f);
    __syncthreads();

    // ---- g2 ----
    {
        int col = tid & 255, half = tid >> 8;
        float acc = 0.0f;
        int kb = half << 7;
#pragma unroll 8
        for (int k = kb; k < kb + 128; k++)
            acc = fmaf(ws[WS_A1 + k], g2w[k * 256 + col], acc);
        ws[WS_T2 + tid] = acc;
    }
    __syncthreads();
    float val = 0.0f;
    if (tid < 256)
        val = ws[WS_T2 + tid] + ws[WS_T2 + 256 + tid] + g2b[tid];

    // ---- LayerNorm ----
    float s1 = val;
#pragma unroll
    for (int off = 16; off; off >>= 1) s1 += __shfl_xor_sync(0xffffffffu, s1, off);
    if (lane == 0) ws[WS_RED + wid] = s1;
    __syncthreads();
    float mu = 0.0f;
#pragma unroll
    for (int i = 0; i < 8; i++) mu += ws[WS_RED + i];
    mu *= (1.0f / 256.0f);
    __syncthreads();

    float d0 = val - mu;
    float s2 = d0 * d0;
#pragma unroll
    for (int off = 16; off; off >>= 1) s2 += __shfl_xor_sync(0xffffffffu, s2, off);
    if (lane == 0) ws[WS_RED + wid] = s2;
    __syncthreads();
    float var = 0.0f;
#pragma unroll
    for (int i = 0; i < 8; i++) var += ws[WS_RED + i];
    var *= (1.0f / 256.0f);

    if (tid < 256)
        out[b * 256 + tid] = d0 * rsqrtf(var + 1e-5f) * ln_g[tid] + ln_b[tid];
}

// ---------------------------------------------------------------------------
extern "C" void kernel_launch(void* const* d_in, const int* in_sizes, int n_in,
                              void* d_out, int out_size)
{
    const float* obstacles = (const float*)d_in[0];
    const int*   lengths   = (const int*)d_in[1];
    const float* w1   = (const float*)d_in[2];
    const float* b1   = (const float*)d_in[3];
    const float* w2   = (const float*)d_in[4];
    const float* b2   = (const float*)d_in[5];
    const float* pos  = (const float*)d_in[6];
    const float* wq   = (const float*)d_in[7];
    const float* bq   = (const float*)d_in[8];
    const float* wk   = (const float*)d_in[9];
    const float* bk   = (const float*)d_in[10];
    const float* wv   = (const float*)d_in[11];
    const float* bv   = (const float*)d_in[12];
    const float* wo   = (const float*)d_in[13];
    const float* bo   = (const float*)d_in[14];
    const float* g1w  = (const float*)d_in[15];
    const float* g1b  = (const float*)d_in[16];
    const float* g2w  = (const float*)d_in[17];
    const float* g2b  = (const float*)d_in[18];
    const float* ln_g = (const float*)d_in[19];
    const float* ln_b = (const float*)d_in[20];
    float* out = (float*)d_out;

    const int B = in_sizes[1];

    fold_k<<<768, 256>>>(w2, wq, wk, wv);
    posfold_k<<<192, 256>>>(pos, b2, wq, wk, wv, bq, bk, bv);
    pack_k<<<512, 256>>>(wo);

    cudaFuncSetAttribute(enc_kernel, cudaFuncAttributeMaxDynamicSharedMemorySize, SMEM_BYTES);
    enc_kernel<<<B, 512, SMEM_BYTES>>>(
        obstacles, lengths, w1, b1, bo,
        g1w, g1b, g2w, g2b, ln_g, ln_b, out);
}

// round 5
// speedup vs baseline: 1.5173x; 1.0646x over previous
#include <cuda_runtime.h>

// ============================================================================
// AttentionObstacleEncoder via tf32 mma.sync.m16n8k8 (3xTF32 precision).
//
// Fold: h = t@w2 + b2 + pos  =>  Q = t@(w2@wq) + [(pos+b2)@wq + bq]  (etc).
// Prep kernels fold weights / pos-bias and pack weights as tf32 hi/lo uint4.
// Main kernel: one CTA (512 thr) per batch element.
// NEW (R5): t stored pre-split as tf32-hi(u32) + lo(u16 bf16-trunc) so the
// 5 t-consuming GEMM passes need zero CVT on the A side (lo<<16 is tf32).
// ============================================================================

typedef unsigned int u32;
typedef unsigned short u16;

#define LDT 260     // stride (word units) for [64][256] buffers; 260%32==4
#define LDK 68      // stride for [64][64] head buffers

// smem word offsets
#define OFF_TH  0        // t hi  [64][260] u32
#define OFF_TL  16640    // t lo  [64][260] u16 (8320 words)
#define OFF_Q   24960    // Q / ctx [64][260] fp32
#define OFF_K   41600    // K_h  [64][68] fp32
#define OFF_VT  45952    // VT_h [64][68] fp32
#define OFF_S   50304    // S/P  [64][68] fp32  (+ scratch alias)
#define SMEM_WORDS 54656
#define SMEM_BYTES (SMEM_WORDS * 4)

// scratch sub-offsets inside S region (floats)
#define WS_PS   0
#define WS_PM   512
#define WS_G    1024
#define WS_T1   1536
#define WS_A1   2048
#define WS_T2   2304
#define WS_RED  2816
#define WS_OBS  2848
#define WS_W1   3104

// device scratch
__device__ float g_wf[3 * 65536];        // w2@{wq,wk,wv} fp32 (q pre-scaled 1/8)
__device__ float g_posb[3 * 16384];      // [(pos+b2)@wx + bx] per-row bias
__device__ uint4 g_wr[4 * 32768];        // packed tf32 hi/lo: {wq',wk',wv',wo}

__device__ __forceinline__ u32 cvt_tf32(float f) {
    u32 r; asm("cvt.rna.tf32.f32 %0, %1;" : "=r"(r) : "f"(f)); return r;
}
__device__ __forceinline__ void hilo(float x, u32& h, u32& l) {
    h = cvt_tf32(x);
    l = cvt_tf32(x - __uint_as_float(h));
}
__device__ __forceinline__ void mma8(float* c, u32 a0, u32 a1, u32 a2, u32 a3,
                                     u32 b0, u32 b1) {
    asm("mma.sync.aligned.m16n8k8.row.col.f32.tf32.tf32.f32 "
        "{%0,%1,%2,%3},{%4,%5,%6,%7},{%8,%9},{%0,%1,%2,%3};"
        : "+f"(c[0]), "+f"(c[1]), "+f"(c[2]), "+f"(c[3])
        : "r"(a0), "r"(a1), "r"(a2), "r"(a3), "r"(b0), "r"(b1));
}
__device__ __forceinline__ void mma3(float* c, const u32* ah, const u32* al,
                                     u32 bh0, u32 bh1, u32 bl0, u32 bl1) {
    mma8(c, al[0], al[1], al[2], al[3], bh0, bh1);
    mma8(c, ah[0], ah[1], ah[2], ah[3], bl0, bl1);
    mma8(c, ah[0], ah[1], ah[2], ah[3], bh0, bh1);
}

// ============================================================================
// Prep kernels (per launch, deterministic, ~25us)
// ============================================================================

__global__ void fold_k(const float* __restrict__ w2, const float* __restrict__ wq,
                       const float* __restrict__ wk, const float* __restrict__ wv)
{
    int m = blockIdx.x >> 8, k = blockIdx.x & 255, c = threadIdx.x;
    const float* wx = (m == 0) ? wq : (m == 1) ? wk : wv;
    float acc = 0.0f;
#pragma unroll 8
    for (int d = 0; d < 256; d++)
        acc = fmaf(__ldg(w2 + k * 256 + d), __ldg(wx + d * 256 + c), acc);
    if (m == 0) acc *= 0.125f;
    g_wf[m * 65536 + k * 256 + c] = acc;
}

__global__ void posfold_k(const float* __restrict__ pos, const float* __restrict__ b2,
                          const float* __restrict__ wq, const float* __restrict__ wk,
                          const float* __restrict__ wv, const float* __restrict__ bq,
                          const float* __restrict__ bk, const float* __restrict__ bv)
{
    int m = blockIdx.x >> 6, n = blockIdx.x & 63, c = threadIdx.x;
    const float* wx = (m == 0) ? wq : (m == 1) ? wk : wv;
    const float* bx = (m == 0) ? bq : (m == 1) ? bk : bv;
    float acc = __ldg(bx + c);
#pragma unroll 8
    for (int d = 0; d < 256; d++)
        acc = fmaf(__ldg(pos + n * 256 + d) + __ldg(b2 + d), __ldg(wx + d * 256 + c), acc);
    if (m == 0) acc *= 0.125f;
    g_posb[m * 16384 + n * 256 + c] = acc;
}

__global__ void pack_k(const float* __restrict__ wo)
{
    int idx = blockIdx.x * 256 + threadIdx.x;      // 0 .. 131071
    int m = idx >> 15;
    int u = idx & 32767;
    int ntile = u >> 10;
    int s = (u >> 5) & 31;
    int lane = u & 31;
    int n = ntile * 8 + (lane >> 2);
    int k = s * 8 + (lane & 3);
    const float* W = (m < 3) ? (g_wf + m * 65536) : wo;
    float b0 = W[k * 256 + n];
    float b1 = W[(k + 4) * 256 + n];
    uint4 r;
    hilo(b0, r.x, r.y);
    hilo(b1, r.z, r.w);
    g_wr[idx] = r;
}

// ============================================================================
// Device GEMM pieces
// ============================================================================

// A fragment from pre-split hi(u32)/lo(u16) buffers — zero CVT.
__device__ __forceinline__ void load_a_pair(
    const u32* Th, const u16* Tl, int m0, int k0, int g, int t,
    u32* ah, u32* al)
{
    int e0 = (m0 + g) * LDT + k0 + t;
    int e1 = (m0 + 8 + g) * LDT + k0 + t;
    ah[0] = Th[e0];     al[0] = ((u32)Tl[e0]) << 16;
    ah[1] = Th[e1];     al[1] = ((u32)Tl[e1]) << 16;
    ah[2] = Th[e0 + 4]; al[2] = ((u32)Tl[e0 + 4]) << 16;
    ah[3] = Th[e1 + 4]; al[3] = ((u32)Tl[e1 + 4]) << 16;
}

// A fragment from fp32 buffer — on-the-fly split (WO / small GEMMs only).
__device__ __forceinline__ void load_a_f32(const float* A, int ld, int m0, int k0,
                                           int g, int t, u32* ah, u32* al)
{
    float a0 = A[(m0 + g) * ld + k0 + t];
    float a1 = A[(m0 + 8 + g) * ld + k0 + t];
    float a2 = A[(m0 + g) * ld + k0 + 4 + t];
    float a3 = A[(m0 + 8 + g) * ld + k0 + 4 + t];
    hilo(a0, ah[0], al[0]);
    hilo(a1, ah[1], al[1]);
    hilo(a2, ah[2], al[2]);
    hilo(a3, ah[3], al[3]);
}

// Big GEMM (pair A): Out[64][256] = T @ W(packed) + biasRows.
__device__ __forceinline__ void gemm_big_pair(
    const u32* Th, const u16* Tl, const uint4* __restrict__ Wp,
    const float* __restrict__ biasRows, float* Out)
{
    const int wid = threadIdx.x >> 5, lane = threadIdx.x & 31;
    const int g = lane >> 2, t = lane & 3;
    const int m0 = (wid & 3) << 4;
    const int ncol = wid >> 2;
    const int ntbase = ncol << 3;

    float c[8][4];
#pragma unroll
    for (int i = 0; i < 8; i++)
#pragma unroll
        for (int j = 0; j < 4; j++) c[i][j] = 0.0f;

#pragma unroll 2
    for (int s = 0; s < 32; s++) {
        u32 ah[4], al[4];
        load_a_pair(Th, Tl, m0, s << 3, g, t, ah, al);
#pragma unroll
        for (int half = 0; half < 2; half++) {
            uint4 w[4];
#pragma unroll
            for (int i = 0; i < 4; i++)
                w[i] = Wp[((ntbase + half * 4 + i) << 10) + (s << 5) + lane];
#pragma unroll
            for (int i = 0; i < 4; i++)
                mma3(c[half * 4 + i], ah, al, w[i].x, w[i].z, w[i].y, w[i].w);
        }
    }

#pragma unroll
    for (int nt = 0; nt < 8; nt++) {
        int col = (ncol << 6) + (nt << 3) + (t << 1);
        float2 bA = *(const float2*)(biasRows + (m0 + g) * 256 + col);
        float2 bB = *(const float2*)(biasRows + (m0 + 8 + g) * 256 + col);
        Out[(m0 + g) * LDT + col]         = c[nt][0] + bA.x;
        Out[(m0 + g) * LDT + col + 1]     = c[nt][1] + bA.y;
        Out[(m0 + 8 + g) * LDT + col]     = c[nt][2] + bB.x;
        Out[(m0 + 8 + g) * LDT + col + 1] = c[nt][3] + bB.y;
    }
}

// Big GEMM (fp32 A): Out = A @ W(packed) + biasVec  (WO pass).
__device__ __forceinline__ void gemm_big_f32(
    const float* A, const uint4* __restrict__ Wp,
    const float* __restrict__ biasVec, float* Out)
{
    const int wid = threadIdx.x >> 5, lane = threadIdx.x & 31;
    const int g = lane >> 2, t = lane & 3;
    const int m0 = (wid & 3) << 4;
    const int ncol = wid >> 2;
    const int ntbase = ncol << 3;

    float c[8][4];
#pragma unroll
    for (int i = 0; i < 8; i++)
#pragma unroll
        for (int j = 0; j < 4; j++) c[i][j] = 0.0f;

#pragma unroll 2
    for (int s = 0; s < 32; s++) {
        u32 ah[4], al[4];
        load_a_f32(A, LDT, m0, s << 3, g, t, ah, al);
#pragma unroll
        for (int half = 0; half < 2; half++) {
            uint4 w[4];
#pragma unroll
            for (int i = 0; i < 4; i++)
                w[i] = Wp[((ntbase + half * 4 + i) << 10) + (s << 5) + lane];
#pragma unroll
            for (int i = 0; i < 4; i++)
                mma3(c[half * 4 + i], ah, al, w[i].x, w[i].z, w[i].y, w[i].w);
        }
    }

#pragma unroll
    for (int nt = 0; nt < 8; nt++) {
        int col = (ncol << 6) + (nt << 3) + (t << 1);
        float2 bb = *(const float2*)(biasVec + col);
        Out[(m0 + g) * LDT + col]         = c[nt][0] + bb.x;
        Out[(m0 + g) * LDT + col + 1]     = c[nt][1] + bb.y;
        Out[(m0 + 8 + g) * LDT + col]     = c[nt][2] + bb.x;
        Out[(m0 + 8 + g) * LDT + col + 1] = c[nt][3] + bb.y;
    }
}

// Per-head K/V: warps 0-7 -> K_h [64][68]; warps 8-15 -> VT_h (transposed).
__device__ __forceinline__ void gemm_kv(
    const u32* Th, const u16* Tl, int h, float* Kh, float* VTh)
{
    const int wid = threadIdx.x >> 5, lane = threadIdx.x & 31;
    const int g = lane >> 2, t = lane & 3;
    const int lw = wid & 7, isV = wid >> 3;
    const int m0 = (lw & 3) << 4;
    const int ncol2 = lw >> 2;
    const uint4* __restrict__ Wp = g_wr + ((1 + isV) << 15);
    const float* __restrict__ biasRows = g_posb + ((1 + isV) << 14);

    float c[4][4];
#pragma unroll
    for (int i = 0; i < 4; i++)
#pragma unroll
        for (int j = 0; j < 4; j++) c[i][j] = 0.0f;

#pragma unroll 2
    for (int s = 0; s < 32; s++) {
        u32 ah[4], al[4];
        load_a_pair(Th, Tl, m0, s << 3, g, t, ah, al);
        uint4 w[4];
#pragma unroll
        for (int i = 0; i < 4; i++) {
            int ntg = (h << 3) + (ncol2 << 2) + i;
            w[i] = Wp[(ntg << 10) + (s << 5) + lane];
        }
#pragma unroll
        for (int i = 0; i < 4; i++)
            mma3(c[i], ah, al, w[i].x, w[i].z, w[i].y, w[i].w);
    }

#pragma unroll
    for (int nt = 0; nt < 4; nt++) {
        int nl = (ncol2 << 5) + (nt << 3) + (t << 1);
        int colg = (h << 6) + nl;
        float2 bA = *(const float2*)(biasRows + (m0 + g) * 256 + colg);
        float2 bB = *(const float2*)(biasRows + (m0 + 8 + g) * 256 + colg);
        if (!isV) {
            Kh[(m0 + g) * LDK + nl]         = c[nt][0] + bA.x;
            Kh[(m0 + g) * LDK + nl + 1]     = c[nt][1] + bA.y;
            Kh[(m0 + 8 + g) * LDK + nl]     = c[nt][2] + bB.x;
            Kh[(m0 + 8 + g) * LDK + nl + 1] = c[nt][3] + bB.y;
        } else {
            VTh[nl * LDK + m0 + g]           = c[nt][0] + bA.x;
            VTh[(nl + 1) * LDK + m0 + g]     = c[nt][1] + bA.y;
            VTh[nl * LDK + m0 + 8 + g]       = c[nt][2] + bB.x;
            VTh[(nl + 1) * LDK + m0 + 8 + g] = c[nt][3] + bB.y;
        }
    }
}

// 64x64x64 smem GEMM: Out[m][n] = A[m][k] * Bm[n][k].
__device__ __forceinline__ void gemm_small(
    const float* A, int lda, int colA, const float* Bm,
    float* Out, int ldo, int colO)
{
    const int wid = threadIdx.x >> 5, lane = threadIdx.x & 31;
    const int g = lane >> 2, t = lane & 3;
    const int m0 = (wid & 3) << 4;
    const int ncol = wid >> 2;

    float c[2][4];
#pragma unroll
    for (int i = 0; i < 2; i++)
#pragma unroll
        for (int j = 0; j < 4; j++) c[i][j] = 0.0f;

#pragma unroll 2
    for (int s = 0; s < 8; s++) {
        int k0 = s << 3;
        u32 ah[4], al[4];
        load_a_f32(A + colA, lda, m0, k0, g, t, ah, al);
#pragma unroll
        for (int nt = 0; nt < 2; nt++) {
            int n0 = (ncol << 4) + (nt << 3);
            float b0f = Bm[(n0 + g) * LDK + k0 + t];
            float b1f = Bm[(n0 + g) * LDK + k0 + 4 + t];
            u32 bh0, bl0, bh1, bl1;
            hilo(b0f, bh0, bl0);
            hilo(b1f, bh1, bl1);
            mma3(c[nt], ah, al, bh0, bh1, bl0, bl1);
        }
    }

#pragma unroll
    for (int nt = 0; nt < 2; nt++) {
        int n0 = (ncol << 4) + (nt << 3) + (t << 1);
        Out[(m0 + g) * ldo + colO + n0]         = c[nt][0];
        Out[(m0 + g) * ldo + colO + n0 + 1]     = c[nt][1];
        Out[(m0 + 8 + g) * ldo + colO + n0]     = c[nt][2];
        Out[(m0 + 8 + g) * ldo + colO + n0 + 1] = c[nt][3];
    }
}

// ============================================================================
__global__ void __launch_bounds__(512, 1)
enc_kernel(const float* __restrict__ obstacles, const int* __restrict__ lengths,
           const float* __restrict__ w1, const float* __restrict__ b1,
           const float* __restrict__ bo,
           const float* __restrict__ g1w, const float* __restrict__ g1b,
           const float* __restrict__ g2w, const float* __restrict__ g2b,
           const float* __restrict__ ln_g, const float* __restrict__ ln_b,
           float* __restrict__ out)
{
    extern __shared__ float sm[];
    u32*   Th  = (u32*)(sm + OFF_TH);
    u16*   Tl  = (u16*)(sm + OFF_TL);
    float* Qs  = sm + OFF_Q;
    float* Kh  = sm + OFF_K;
    float* VTh = sm + OFF_VT;
    float* Ss  = sm + OFF_S;
    float* ws  = sm + OFF_S;       // scratch alias
    float* OutT = sm + OFF_TH;     // WO output reuses T region (fp32)

    const int b   = blockIdx.x;
    const int tid = threadIdx.x;
    const int len = lengths[b];
    const int wid = tid >> 5, lane = tid & 31;

    // ---- stage w1 + obstacles ----
    if (tid < 256) {
        *(float4*)(ws + WS_W1 + (tid << 2)) = *(const float4*)(w1 + (tid << 2));
        ws[WS_OBS + tid] = obstacles[b * 256 + tid];
    }
    __syncthreads();

    // ---- phase 1: t = relu(obs @ w1 + b1) -> Th/Tl pre-split ----
    {
        int col = tid & 255, rh = tid >> 8;
        float wa = ws[WS_W1 + col], wb = ws[WS_W1 + 256 + col];
        float wc_ = ws[WS_W1 + 512 + col], wd = ws[WS_W1 + 768 + col];
        float bb = b1[col];
        int n0 = rh << 5;
#pragma unroll 8
        for (int n = n0; n < n0 + 32; n++) {
            float4 o = *(const float4*)(ws + WS_OBS + (n << 2));
            float v = fmaf(o.x, wa, fmaf(o.y, wb, fmaf(o.z, wc_, fmaf(o.w, wd, bb))));
            v = fmaxf(v, 0.0f);
            u32 hi = cvt_tf32(v);
            float lf = v - __uint_as_float(hi);
            Th[n * LDT + col] = hi;
            Tl[n * LDT + col] = (u16)(__float_as_uint(lf) >> 16);
        }
    }
    __syncthreads();

    // ---- Q = t @ wq' + posbq  (1/8 scale folded) ----
    gemm_big_pair(Th, Tl, g_wr, g_posb, Qs);
    __syncthreads();

    // ---- attention heads ----
#pragma unroll 1
    for (int h = 0; h < 4; h++) {
        gemm_kv(Th, Tl, h, Kh, VTh);
        __syncthreads();

        gemm_small(Qs, LDT, h << 6, Kh, Ss, LDK, 0);
        __syncthreads();

        // masked softmax (warp wid owns rows 4*wid..+3)
        {
            bool v0 = lane < len;
            bool v1 = (lane + 32) < len;
#pragma unroll
            for (int rr = 0; rr < 4; rr++) {
                int r = (wid << 2) + rr;
                float x0 = Ss[r * LDK + lane];
                float x1 = Ss[r * LDK + lane + 32];
                float m = fmaxf(v0 ? x0 : -3.4e38f, v1 ? x1 : -3.4e38f);
#pragma unroll
                for (int off = 16; off; off >>= 1)
                    m = fmaxf(m, __shfl_xor_sync(0xffffffffu, m, off));
                float e0 = v0 ? __expf(x0 - m) : 0.0f;
                float e1 = v1 ? __expf(x1 - m) : 0.0f;
                float s = e0 + e1;
#pragma unroll
                for (int off = 16; off; off >>= 1)
                    s += __shfl_xor_sync(0xffffffffu, s, off);
                float inv = __frcp_rn(s);
                Ss[r * LDK + lane] = e0 * inv;
                Ss[r * LDK + lane + 32] = e1 * inv;
            }
        }
        __syncthreads();

        // ctx_h = P @ V_h -> Q cols [64h, +64)
        gemm_small(Ss, LDK, 0, VTh, Qs, LDT, h << 6);
        __syncthreads();
    }

    // ---- out = ctx @ wo + bo -> OutT (T region, fp32) ----
    gemm_big_f32(Qs, g_wr + 3 * 32768, bo, OutT);
    __syncthreads();

    // ---- masked mean/max pool ----
    {
        int col = tid & 255, half = tid >> 8;
        int mid = (len + 1) >> 1;
        int nb = half ? mid : 0, ne = half ? len : mid;
        float s = 0.0f, mx = -3.4e38f;
        for (int n = nb; n < ne; n++) {
            float x = OutT[n * LDT + col];
            s += x; mx = fmaxf(mx, x);
        }
        ws[WS_PS + tid] = s;
        ws[WS_PM + tid] = mx;
    }
    __syncthreads();
    if (tid < 256) {
        ws[WS_G + tid]       = (ws[WS_PS + tid] + ws[WS_PS + 256 + tid]) / (float)len;
        ws[WS_G + 256 + tid] = fmaxf(ws[WS_PM + tid], ws[WS_PM + 256 + tid]);
    }
    __syncthreads();

    // ---- g1 ----
    {
        int col = tid & 255, half = tid >> 8;
        float acc = 0.0f;
        int kb = half << 8;
#pragma unroll 8
        for (int k = kb; k < kb + 256; k++)
            acc = fmaf(ws[WS_G + k], g1w[k * 256 + col], acc);
        ws[WS_T1 + tid] = acc;
    }
    __syncthreads();
    if (tid < 256)
        ws[WS_A1 + tid] = fmaxf(ws[WS_T1 + tid] + ws[WS_T1 + 256 + tid] + g1b[tid], 0.0f);
    __syncthreads();

    // ---- g2 ----
    {
        int col = tid & 255, half = tid >> 8;
        float acc = 0.0f;
        int kb = half << 7;
#pragma unroll 8
        for (int k = kb; k < kb + 128; k++)
            acc = fmaf(ws[WS_A1 + k], g2w[k * 256 + col], acc);
        ws[WS_T2 + tid] = acc;
    }
    __syncthreads();
    float val = 0.0f;
    if (tid < 256)
        val = ws[WS_T2 + tid] + ws[WS_T2 + 256 + tid] + g2b[tid];

    // ---- LayerNorm ----
    float s1 = val;
#pragma unroll
    for (int off = 16; off; off >>= 1) s1 += __shfl_xor_sync(0xffffffffu, s1, off);
    if (lane == 0) ws[WS_RED + wid] = s1;
    __syncthreads();
    float mu = 0.0f;
#pragma unroll
    for (int i = 0; i < 8; i++) mu += ws[WS_RED + i];
    mu *= (1.0f / 256.0f);
    __syncthreads();

    float d0 = val - mu;
    float s2 = d0 * d0;
#pragma unroll
    for (int off = 16; off; off >>= 1) s2 += __shfl_xor_sync(0xffffffffu, s2, off);
    if (lane == 0) ws[WS_RED + wid] = s2;
    __syncthreads();
    float var = 0.0f;
#pragma unroll
    for (int i = 0; i < 8; i++) var += ws[WS_RED + i];
    var *= (1.0f / 256.0f);

    if (tid < 256)
        out[b * 256 + tid] = d0 * rsqrtf(var + 1e-5f) * ln_g[tid] + ln_b[tid];
}

// ---------------------------------------------------------------------------
extern "C" void kernel_launch(void* const* d_in, const int* in_sizes, int n_in,
                              void* d_out, int out_size)
{
    const float* obstacles = (const float*)d_in[0];
    const int*   lengths   = (const int*)d_in[1];
    const float* w1   = (const float*)d_in[2];
    const float* b1   = (const float*)d_in[3];
    const float* w2   = (const float*)d_in[4];
    const float* b2   = (const float*)d_in[5];
    const float* pos  = (const float*)d_in[6];
    const float* wq   = (const float*)d_in[7];
    const float* bq   = (const float*)d_in[8];
    const float* wk   = (const float*)d_in[9];
    const float* bk   = (const float*)d_in[10];
    const float* wv   = (const float*)d_in[11];
    const float* bv   = (const float*)d_in[12];
    const float* wo   = (const float*)d_in[13];
    const float* bo   = (const float*)d_in[14];
    const float* g1w  = (const float*)d_in[15];
    const float* g1b  = (const float*)d_in[16];
    const float* g2w  = (const float*)d_in[17];
    const float* g2b  = (const float*)d_in[18];
    const float* ln_g = (const float*)d_in[19];
    const float* ln_b = (const float*)d_in[20];
    float* out = (float*)d_out;

    const int B = in_sizes[1];

    fold_k<<<768, 256>>>(w2, wq, wk, wv);
    posfold_k<<<192, 256>>>(pos, b2, wq, wk, wv, bq, bk, bv);
    pack_k<<<512, 256>>>(wo);

    cudaFuncSetAttribute(enc_kernel, cudaFuncAttributeMaxDynamicSharedMemorySize, SMEM_BYTES);
    enc_kernel<<<B, 512, SMEM_BYTES>>>(
        obstacles, lengths, w1, b1, bo,
        g1w, g1b, g2w, g2b, ln_g, ln_b, out);
}

// round 7
// speedup vs baseline: 2.6961x; 1.7769x over previous
#include <cuda_runtime.h>

// ============================================================================
// AttentionObstacleEncoder via bf16 mma.sync.m16n8k16, 3-term hi/lo split
// (ah*bh + ah*bl + al*bh; ~17 mantissa bits effective).
//
// Fold: h = t@w2 + b2 + pos  =>  Q = t@(w2@wq) + [(pos+b2)@wq + bq]  (etc).
// Prep kernels fold weights / pos-bias and pack weights as bf16 hi/lo uint4.
// Main kernel: one CTA (512 thr) per batch element. All MMA operands in smem
// are stored PRE-SPLIT as packed bf16x2 words -> zero CVT in GEMM inner loops
// (only V's B-side splits on the fly).
// R7 fix: correct smem sizing (each packed [64][256] buffer = 8448 words);
// OutT aliases the dead T region to fit in 207 KB.
// ============================================================================

typedef unsigned int u32;

#define LDW  132    // u32-word row stride for packed [64][256] arrays (132%32==4)
#define LDWK 36     // u32-word row stride for packed [64][64] arrays  (36%32==4)
#define LDF  68     // fp32 row stride for [64][64] buffers
#define LDO  260    // fp32 row stride for OutT [64][256]

// smem word offsets (u32/float units)
#define OFF_THH  0        // t hi packed  [64][LDW] = 8448 words
#define OFF_THL  8448
#define OFF_QHH  16896    // Q/ctx hi packed
#define OFF_QHL  25344
#define OFF_KHH  33792    // K_h hi packed [64][LDWK] = 2304 words
#define OFF_KHL  36096
#define OFF_PHH  38400    // P hi packed
#define OFF_PHL  40704
#define OFF_VT   43008    // VT_h fp32 [64][LDF] = 4352
#define OFF_S    47360    // scores fp32 [64][LDF] = 4352 (+ scratch alias)
#define OFF_OUT  0        // OutT fp32 [64][LDO] = 16640, ALIASES dead T region
#define SMEM_WORDS 51712
#define SMEM_BYTES (SMEM_WORDS * 4)   // 206848 bytes

// scratch sub-offsets inside S region (floats)
#define WS_PS   0
#define WS_PM   512
#define WS_G    1024
#define WS_T1   1536
#define WS_A1   2048
#define WS_T2   2304
#define WS_RED  2816
#define WS_OBS  2848
#define WS_W1   3104     // 1024 floats, ends at 4128 <= 4352

// device scratch
__device__ float g_wf[3 * 65536];        // w2@{wq,wk,wv} fp32 (q pre-scaled 1/8)
__device__ float g_posb[3 * 16384];      // [(pos+b2)@wx + bx] per-row bias
__device__ uint4 g_wr[4 * 16384];        // bf16 hi/lo packed: {wq',wk',wv',wo}

__device__ __forceinline__ u32 packbf(float x0, float x1) {
    u32 r; asm("cvt.rn.bf16x2.f32 %0, %2, %1;" : "=r"(r) : "f"(x0), "f"(x1));
    return r;    // low half = bf16(x0), high half = bf16(x1)
}
__device__ __forceinline__ void bsplit(float x0, float x1, u32& hw, u32& lw) {
    hw = packbf(x0, x1);
    float h0 = __uint_as_float(hw << 16);
    float h1 = __uint_as_float(hw & 0xffff0000u);
    lw = packbf(x0 - h0, x1 - h1);
}
__device__ __forceinline__ void mmab(float* c, u32 a0, u32 a1, u32 a2, u32 a3,
                                     u32 b0, u32 b1) {
    asm("mma.sync.aligned.m16n8k16.row.col.f32.bf16.bf16.f32 "
        "{%0,%1,%2,%3},{%4,%5,%6,%7},{%8,%9},{%0,%1,%2,%3};"
        : "+f"(c[0]), "+f"(c[1]), "+f"(c[2]), "+f"(c[3])
        : "r"(a0), "r"(a1), "r"(a2), "r"(a3), "r"(b0), "r"(b1));
}
__device__ __forceinline__ void mmab3(float* c, const u32* ah, const u32* al,
                                      u32 bh0, u32 bh1, u32 bl0, u32 bl1) {
    mmab(c, ah[0], ah[1], ah[2], ah[3], bl0, bl1);
    mmab(c, al[0], al[1], al[2], al[3], bh0, bh1);
    mmab(c, ah[0], ah[1], ah[2], ah[3], bh0, bh1);
}

// ============================================================================
// Prep kernels (per launch, deterministic)
// ============================================================================

__global__ void fold_k(const float* __restrict__ w2, const float* __restrict__ wq,
                       const float* __restrict__ wk, const float* __restrict__ wv)
{
    int m = blockIdx.x >> 8, k = blockIdx.x & 255, c = threadIdx.x;
    const float* wx = (m == 0) ? wq : (m == 1) ? wk : wv;
    float acc = 0.0f;
#pragma unroll 8
    for (int d = 0; d < 256; d++)
        acc = fmaf(__ldg(w2 + k * 256 + d), __ldg(wx + d * 256 + c), acc);
    if (m == 0) acc *= 0.125f;
    g_wf[m * 65536 + k * 256 + c] = acc;
}

__global__ void posfold_k(const float* __restrict__ pos, const float* __restrict__ b2,
                          const float* __restrict__ wq, const float* __restrict__ wk,
                          const float* __restrict__ wv, const float* __restrict__ bq,
                          const float* __restrict__ bk, const float* __restrict__ bv)
{
    int m = blockIdx.x >> 6, n = blockIdx.x & 63, c = threadIdx.x;
    const float* wx = (m == 0) ? wq : (m == 1) ? wk : wv;
    const float* bx = (m == 0) ? bq : (m == 1) ? bk : bv;
    float acc = __ldg(bx + c);
#pragma unroll 8
    for (int d = 0; d < 256; d++)
        acc = fmaf(__ldg(pos + n * 256 + d) + __ldg(b2 + d), __ldg(wx + d * 256 + c), acc);
    if (m == 0) acc *= 0.125f;
    g_posb[m * 16384 + n * 256 + c] = acc;
}

// Pack W[256][256] into m16n8k16 B fragments: per (mat, ntile<32, s<16, lane):
//   b0 pair = W[16s+2t +0/+1][8nt+g],  b1 pair = W[16s+2t+8/+9][8nt+g]
//   uint4 = (bh0, bh1, bl0, bl1).  grid 256 x 256.
__global__ void pack_k(const float* __restrict__ wo)
{
    int idx = blockIdx.x * 256 + threadIdx.x;   // 0 .. 65535
    int m = idx >> 14;
    int u = idx & 16383;
    int ntile = u >> 9;
    int s = (u >> 5) & 15;
    int lane = u & 31;
    int g = lane >> 2, t = lane & 3;
    int n = ntile * 8 + g;
    int k0 = s * 16 + t * 2;
    const float* W = (m < 3) ? (g_wf + m * 65536) : wo;
    float f0 = W[k0 * 256 + n];
    float f1 = W[(k0 + 1) * 256 + n];
    float f2 = W[(k0 + 8) * 256 + n];
    float f3 = W[(k0 + 9) * 256 + n];
    uint4 r;
    bsplit(f0, f1, r.x, r.z);
    bsplit(f2, f3, r.y, r.w);
    g_wr[idx] = r;
}

// ============================================================================
// Device GEMM pieces
// ============================================================================

// A fragment (m16 at m0, k16 slab s) from packed hi/lo word arrays.
__device__ __forceinline__ void load_a(const u32* Ah, const u32* Al, int ldw,
                                       int m0, int base, int s, int g, int t,
                                       u32* ah, u32* al)
{
    int e0 = (m0 + g) * ldw + base + (s << 3) + t;
    int e1 = (m0 + 8 + g) * ldw + base + (s << 3) + t;
    ah[0] = Ah[e0]; ah[1] = Ah[e1]; ah[2] = Ah[e0 + 4]; ah[3] = Ah[e1 + 4];
    al[0] = Al[e0]; al[1] = Al[e1]; al[2] = Al[e0 + 4]; al[3] = Al[e1 + 4];
}

// Big GEMM: Out[64][256] = T(packed) @ Wp + bias.
// PACKOUT: pack into Ohh/Ohl with per-row bias table; else fp32 -> Ofp + biasVec.
template<bool PACKOUT>
__device__ __forceinline__ void gemm_big(
    const u32* Ah, const u32* Al, const uint4* __restrict__ Wp,
    const float* __restrict__ biasRows, const float* __restrict__ biasVec,
    u32* Ohh, u32* Ohl, float* Ofp)
{
    const int wid = threadIdx.x >> 5, lane = threadIdx.x & 31;
    const int g = lane >> 2, t = lane & 3;
    const int m0 = (wid & 3) << 4;
    const int ncol = wid >> 2;
    const int ntbase = ncol << 3;

    float c[8][4];
#pragma unroll
    for (int i = 0; i < 8; i++)
#pragma unroll
        for (int j = 0; j < 4; j++) c[i][j] = 0.0f;

#pragma unroll 2
    for (int s = 0; s < 16; s++) {
        u32 ah[4], al[4];
        load_a(Ah, Al, LDW, m0, 0, s, g, t, ah, al);
#pragma unroll
        for (int i = 0; i < 8; i++) {
            uint4 w = Wp[((ntbase + i) << 9) + (s << 5) + lane];
            mmab3(c[i], ah, al, w.x, w.y, w.z, w.w);
        }
    }

#pragma unroll
    for (int nt = 0; nt < 8; nt++) {
        int col = (ncol << 6) + (nt << 3) + (t << 1);
        if (PACKOUT) {
            float2 bA = *(const float2*)(biasRows + (m0 + g) * 256 + col);
            float2 bB = *(const float2*)(biasRows + (m0 + 8 + g) * 256 + col);
            u32 hw, lw;
            bsplit(c[nt][0] + bA.x, c[nt][1] + bA.y, hw, lw);
            Ohh[(m0 + g) * LDW + (col >> 1)] = hw;
            Ohl[(m0 + g) * LDW + (col >> 1)] = lw;
            bsplit(c[nt][2] + bB.x, c[nt][3] + bB.y, hw, lw);
            Ohh[(m0 + 8 + g) * LDW + (col >> 1)] = hw;
            Ohl[(m0 + 8 + g) * LDW + (col >> 1)] = lw;
        } else {
            float2 bb = *(const float2*)(biasVec + col);
            *(float2*)(Ofp + (m0 + g) * LDO + col) =
                make_float2(c[nt][0] + bb.x, c[nt][1] + bb.y);
            *(float2*)(Ofp + (m0 + 8 + g) * LDO + col) =
                make_float2(c[nt][2] + bb.x, c[nt][3] + bb.y);
        }
    }
}

// Per-head K/V: warps 0-7 -> K_h packed hi/lo; warps 8-15 -> VT_h fp32 transposed.
__device__ __forceinline__ void gemm_kv(
    const u32* Ah, const u32* Al, int h,
    u32* Khh, u32* Khl, float* VTh)
{
    const int wid = threadIdx.x >> 5, lane = threadIdx.x & 31;
    const int g = lane >> 2, t = lane & 3;
    const int lw_ = wid & 7, isV = wid >> 3;
    const int m0 = (lw_ & 3) << 4;
    const int ncol2 = lw_ >> 2;
    const uint4* __restrict__ Wp = g_wr + ((1 + isV) << 14);
    const float* __restrict__ biasRows = g_posb + ((1 + isV) << 14);

    float c[4][4];
#pragma unroll
    for (int i = 0; i < 4; i++)
#pragma unroll
        for (int j = 0; j < 4; j++) c[i][j] = 0.0f;

#pragma unroll 2
    for (int s = 0; s < 16; s++) {
        u32 ah[4], al[4];
        load_a(Ah, Al, LDW, m0, 0, s, g, t, ah, al);
#pragma unroll
        for (int i = 0; i < 4; i++) {
            int ntg = (h << 3) + (ncol2 << 2) + i;
            uint4 w = Wp[(ntg << 9) + (s << 5) + lane];
            mmab3(c[i], ah, al, w.x, w.y, w.z, w.w);
        }
    }

#pragma unroll
    for (int nt = 0; nt < 4; nt++) {
        int nl = (ncol2 << 5) + (nt << 3) + (t << 1);
        int colg = (h << 6) + nl;
        float2 bA = *(const float2*)(biasRows + (m0 + g) * 256 + colg);
        float2 bB = *(const float2*)(biasRows + (m0 + 8 + g) * 256 + colg);
        if (!isV) {
            u32 hw, lww;
            bsplit(c[nt][0] + bA.x, c[nt][1] + bA.y, hw, lww);
            Khh[(m0 + g) * LDWK + (nl >> 1)] = hw;
            Khl[(m0 + g) * LDWK + (nl >> 1)] = lww;
            bsplit(c[nt][2] + bB.x, c[nt][3] + bB.y, hw, lww);
            Khh[(m0 + 8 + g) * LDWK + (nl >> 1)] = hw;
            Khl[(m0 + 8 + g) * LDWK + (nl >> 1)] = lww;
        } else {
            VTh[nl * LDF + m0 + g]           = c[nt][0] + bA.x;
            VTh[(nl + 1) * LDF + m0 + g]     = c[nt][1] + bA.y;
            VTh[nl * LDF + m0 + 8 + g]       = c[nt][2] + bB.x;
            VTh[(nl + 1) * LDF + m0 + 8 + g] = c[nt][3] + bB.y;
        }
    }
}

// scores = Q_h(packed) @ K_h(packed)^T -> Ss fp32
__device__ __forceinline__ void gemm_scores(
    const u32* Qhh, const u32* Qhl, int h,
    const u32* Khh, const u32* Khl, float* Ss)
{
    const int wid = threadIdx.x >> 5, lane = threadIdx.x & 31;
    const int g = lane >> 2, t = lane & 3;
    const int m0 = (wid & 3) << 4;
    const int ncol = wid >> 2;

    float c[2][4];
#pragma unroll
    for (int i = 0; i < 2; i++)
#pragma unroll
        for (int j = 0; j < 4; j++) c[i][j] = 0.0f;

#pragma unroll
    for (int s = 0; s < 4; s++) {
        u32 ah[4], al[4];
        load_a(Qhh, Qhl, LDW, m0, h << 5, s, g, t, ah, al);
#pragma unroll
        for (int nt = 0; nt < 2; nt++) {
            int n0 = (ncol << 4) + (nt << 3);
            int kb = (n0 + g) * LDWK + (s << 3) + t;
            mmab3(c[nt], ah, al, Khh[kb], Khh[kb + 4], Khl[kb], Khl[kb + 4]);
        }
    }

#pragma unroll
    for (int nt = 0; nt < 2; nt++) {
        int n0 = (ncol << 4) + (nt << 3) + (t << 1);
        *(float2*)(Ss + (m0 + g) * LDF + n0)     = make_float2(c[nt][0], c[nt][1]);
        *(float2*)(Ss + (m0 + 8 + g) * LDF + n0) = make_float2(c[nt][2], c[nt][3]);
    }
}

// ctx_h = P(packed) @ V_h (VT fp32, B-side split on the fly) -> packed into Q.
__device__ __forceinline__ void gemm_pv(
    const u32* Phh, const u32* Phl, const float* VT, int h,
    u32* Qhh, u32* Qhl)
{
    const int wid = threadIdx.x >> 5, lane = threadIdx.x & 31;
    const int g = lane >> 2, t = lane & 3;
    const int m0 = (wid & 3) << 4;
    const int ncol = wid >> 2;

    float c[2][4];
#pragma unroll
    for (int i = 0; i < 2; i++)
#pragma unroll
        for (int j = 0; j < 4; j++) c[i][j] = 0.0f;

#pragma unroll
    for (int s = 0; s < 4; s++) {
        u32 ah[4], al[4];
        load_a(Phh, Phl, LDWK, m0, 0, s, g, t, ah, al);
#pragma unroll
        for (int nt = 0; nt < 2; nt++) {
            int n0 = (ncol << 4) + (nt << 3);
            float2 v0 = *(const float2*)(VT + (n0 + g) * LDF + (s << 4) + (t << 1));
            float2 v1 = *(const float2*)(VT + (n0 + g) * LDF + (s << 4) + (t << 1) + 8);
            u32 bh0, bl0, bh1, bl1;
            bsplit(v0.x, v0.y, bh0, bl0);
            bsplit(v1.x, v1.y, bh1, bl1);
            mmab3(c[nt], ah, al, bh0, bh1, bl0, bl1);
        }
    }

#pragma unroll
    for (int nt = 0; nt < 2; nt++) {
        int coll = (ncol << 4) + (nt << 3) + (t << 1);
        int wrd = (h << 5) + (coll >> 1);
        u32 hw, lw;
        bsplit(c[nt][0], c[nt][1], hw, lw);
        Qhh[(m0 + g) * LDW + wrd] = hw;
        Qhl[(m0 + g) * LDW + wrd] = lw;
        bsplit(c[nt][2], c[nt][3], hw, lw);
        Qhh[(m0 + 8 + g) * LDW + wrd] = hw;
        Qhl[(m0 + 8 + g) * LDW + wrd] = lw;
    }
}

// ============================================================================
__global__ void __launch_bounds__(512, 1)
enc_kernel(const float* __restrict__ obstacles, const int* __restrict__ lengths,
           const float* __restrict__ w1, const float* __restrict__ b1,
           const float* __restrict__ bo,
           const float* __restrict__ g1w, const float* __restrict__ g1b,
           const float* __restrict__ g2w, const float* __restrict__ g2b,
           const float* __restrict__ ln_g, const float* __restrict__ ln_b,
           float* __restrict__ out)
{
    extern __shared__ float sm[];
    u32* Thh = (u32*)(sm + OFF_THH);
    u32* Thl = (u32*)(sm + OFF_THL);
    u32* Qhh = (u32*)(sm + OFF_QHH);
    u32* Qhl = (u32*)(sm + OFF_QHL);
    u32* Khh = (u32*)(sm + OFF_KHH);
    u32* Khl = (u32*)(sm + OFF_KHL);
    u32* Phh = (u32*)(sm + OFF_PHH);
    u32* Phl = (u32*)(sm + OFF_PHL);
    float* VTh = sm + OFF_VT;
    float* Ss  = sm + OFF_S;
    float* ws  = sm + OFF_S;      // scratch alias (phase-disjoint)
    float* OutT = sm + OFF_OUT;   // aliases T region (T dead by then)

    const int b   = blockIdx.x;
    const int tid = threadIdx.x;
    const int len = lengths[b];
    const int wid = tid >> 5, lane = tid & 31;

    // ---- stage w1 + obstacles into ws scratch ----
    if (tid < 256) {
        *(float4*)(ws + WS_W1 + (tid << 2)) = *(const float4*)(w1 + (tid << 2));
        ws[WS_OBS + tid] = obstacles[b * 256 + tid];
    }
    __syncthreads();

    // ---- phase 1: t = relu(obs @ w1 + b1) -> packed bf16 hi/lo ----
    {
        int cp = tid & 127, q = tid >> 7;       // col pair, row quarter
        int c0 = cp << 1;
        float wa0 = ws[WS_W1 + c0],       wa1 = ws[WS_W1 + c0 + 1];
        float wb0 = ws[WS_W1 + 256 + c0], wb1 = ws[WS_W1 + 256 + c0 + 1];
        float wc0 = ws[WS_W1 + 512 + c0], wc1 = ws[WS_W1 + 512 + c0 + 1];
        float wd0 = ws[WS_W1 + 768 + c0], wd1 = ws[WS_W1 + 768 + c0 + 1];
        float bb0 = b1[c0], bb1 = b1[c0 + 1];
        int n0 = q << 4;
#pragma unroll 4
        for (int n = n0; n < n0 + 16; n++) {
            float4 o = *(const float4*)(ws + WS_OBS + (n << 2));
            float v0 = fmaf(o.x, wa0, fmaf(o.y, wb0, fmaf(o.z, wc0, fmaf(o.w, wd0, bb0))));
            float v1 = fmaf(o.x, wa1, fmaf(o.y, wb1, fmaf(o.z, wc1, fmaf(o.w, wd1, bb1))));
            v0 = fmaxf(v0, 0.0f); v1 = fmaxf(v1, 0.0f);
            u32 hw, lw;
            bsplit(v0, v1, hw, lw);
            Thh[n * LDW + cp] = hw;
            Thl[n * LDW + cp] = lw;
        }
    }
    __syncthreads();

    // ---- Q = t @ wq' + posbq  (1/8 folded), packed output ----
    gemm_big<true>(Thh, Thl, g_wr, g_posb, nullptr, Qhh, Qhl, nullptr);
    __syncthreads();

    // ---- attention heads ----
#pragma unroll 1
    for (int h = 0; h < 4; h++) {
        gemm_kv(Thh, Thl, h, Khh, Khl, VTh);
        __syncthreads();

        gemm_scores(Qhh, Qhl, h, Khh, Khl, Ss);
        __syncthreads();

        // masked softmax: warp wid owns rows 4wid..+3; lane owns cols 2l,2l+1
        {
            bool va = (lane << 1) < len;
            bool vb = ((lane << 1) + 1) < len;
#pragma unroll
            for (int rr = 0; rr < 4; rr++) {
                int r = (wid << 2) + rr;
                float2 x = *(const float2*)(Ss + r * LDF + (lane << 1));
                float m = fmaxf(va ? x.x : -3.4e38f, vb ? x.y : -3.4e38f);
#pragma unroll
                for (int off = 16; off; off >>= 1)
                    m = fmaxf(m, __shfl_xor_sync(0xffffffffu, m, off));
                float e0 = va ? __expf(x.x - m) : 0.0f;
                float e1 = vb ? __expf(x.y - m) : 0.0f;
                float s = e0 + e1;
#pragma unroll
                for (int off = 16; off; off >>= 1)
                    s += __shfl_xor_sync(0xffffffffu, s, off);
                float inv = __frcp_rn(s);
                u32 hw, lw;
                bsplit(e0 * inv, e1 * inv, hw, lw);
                Phh[r * LDWK + lane] = hw;
                Phl[r * LDWK + lane] = lw;
            }
        }
        __syncthreads();

        gemm_pv(Phh, Phl, VTh, h, Qhh, Qhl);
        __syncthreads();
    }

    // ---- out = ctx @ wo + bo -> OutT fp32 (aliases dead T) ----
    gemm_big<false>(Qhh, Qhl, g_wr + 3 * 16384, nullptr, bo, nullptr, nullptr, OutT);
    __syncthreads();

    // ---- masked mean/max pool ----
    {
        int col = tid & 255, half = tid >> 8;
        int mid = (len + 1) >> 1;
        int nb = half ? mid : 0, ne = half ? len : mid;
        float s = 0.0f, mx = -3.4e38f;
        for (int n = nb; n < ne; n++) {
            float x = OutT[n * LDO + col];
            s += x; mx = fmaxf(mx, x);
        }
        ws[WS_PS + tid] = s;
        ws[WS_PM + tid] = mx;
    }
    __syncthreads();
    if (tid < 256) {
        ws[WS_G + tid]       = (ws[WS_PS + tid] + ws[WS_PS + 256 + tid]) / (float)len;
        ws[WS_G + 256 + tid] = fmaxf(ws[WS_PM + tid], ws[WS_PM + 256 + tid]);
    }
    __syncthreads();

    // ---- g1 ----
    {
        int col = tid & 255, half = tid >> 8;
        float acc = 0.0f;
        int kb = half << 8;
#pragma unroll 8
        for (int k = kb; k < kb + 256; k++)
            acc = fmaf(ws[WS_G + k], g1w[k * 256 + col], acc);
        ws[WS_T1 + tid] = acc;
    }
    __syncthreads();
    if (tid < 256)
        ws[WS_A1 + tid] = fmaxf(ws[WS_T1 + tid] + ws[WS_T1 + 256 + tid] + g1b[tid], 0.0f);
    __syncthreads();

    // ---- g2 ----
    {
        int col = tid & 255, half = tid >> 8;
        float acc = 0.0f;
        int kb = half << 7;
#pragma unroll 8
        for (int k = kb; k < kb + 128; k++)
            acc = fmaf(ws[WS_A1 + k], g2w[k * 256 + col], acc);
        ws[WS_T2 + tid] = acc;
    }
    __syncthreads();
    float val = 0.0f;
    if (tid < 256)
        val = ws[WS_T2 + tid] + ws[WS_T2 + 256 + tid] + g2b[tid];

    // ---- LayerNorm ----
    float s1 = val;
#pragma unroll
    for (int off = 16; off; off >>= 1) s1 += __shfl_xor_sync(0xffffffffu, s1, off);
    if (lane == 0) ws[WS_RED + wid] = s1;
    __syncthreads();
    float mu = 0.0f;
#pragma unroll
    for (int i = 0; i < 8; i++) mu += ws[WS_RED + i];
    mu *= (1.0f / 256.0f);
    __syncthreads();

    float d0 = val - mu;
    float s2 = d0 * d0;
#pragma unroll
    for (int off = 16; off; off >>= 1) s2 += __shfl_xor_sync(0xffffffffu, s2, off);
    if (lane == 0) ws[WS_RED + wid] = s2;
    __syncthreads();
    float var = 0.0f;
#pragma unroll
    for (int i = 0; i < 8; i++) var += ws[WS_RED + i];
    var *= (1.0f / 256.0f);

    if (tid < 256)
        out[b * 256 + tid] = d0 * rsqrtf(var + 1e-5f) * ln_g[tid] + ln_b[tid];
}

// ---------------------------------------------------------------------------
extern "C" void kernel_launch(void* const* d_in, const int* in_sizes, int n_in,
                              void* d_out, int out_size)
{
    const float* obstacles = (const float*)d_in[0];
    const int*   lengths   = (const int*)d_in[1];
    const float* w1   = (const float*)d_in[2];
    const float* b1   = (const float*)d_in[3];
    const float* w2   = (const float*)d_in[4];
    const float* b2   = (const float*)d_in[5];
    const float* pos  = (const float*)d_in[6];
    const float* wq   = (const float*)d_in[7];
    const float* bq   = (const float*)d_in[8];
    const float* wk   = (const float*)d_in[9];
    const float* bk   = (const float*)d_in[10];
    const float* wv   = (const float*)d_in[11];
    const float* bv   = (const float*)d_in[12];
    const float* wo   = (const float*)d_in[13];
    const float* bo   = (const float*)d_in[14];
    const float* g1w  = (const float*)d_in[15];
    const float* g1b  = (const float*)d_in[16];
    const float* g2w  = (const float*)d_in[17];
    const float* g2b  = (const float*)d_in[18];
    const float* ln_g = (const float*)d_in[19];
    const float* ln_b = (const float*)d_in[20];
    float* out = (float*)d_out;

    const int B = in_sizes[1];

    fold_k<<<768, 256>>>(w2, wq, wk, wv);
    posfold_k<<<192, 256>>>(pos, b2, wq, wk, wv, bq, bk, bv);
    pack_k<<<256, 256>>>(wo);

    cudaFuncSetAttribute(enc_kernel, cudaFuncAttributeMaxDynamicSharedMemorySize, SMEM_BYTES);
    enc_kernel<<<B, 512, SMEM_BYTES>>>(
        obstacles, lengths, w1, b1, bo,
        g1w, g1b, g2w, g2b, ln_g, ln_b, out);
}